// round 11
// baseline (speedup 1.0000x reference)
#include <cuda_runtime.h>
#include <cuda_fp16.h>
#include <cstdint>

// ---------------------------------------------------------------------------
// Problem constants
// ---------------------------------------------------------------------------
#define B_   8
#define C_   256
#define N_   4096
#define G_   8
#define CPG_ 32
#define EPS_ 1e-5f
#define QSCALE_ 0.09016844270216718f   // log2(e)/sqrt(C)

// ---------------------------------------------------------------------------
// Device scratch
// ---------------------------------------------------------------------------
__device__ __half g_xh[(size_t)B_ * N_ * C_];    // GN-applied x, token-major
__device__ __half g_qh[(size_t)B_ * N_ * C_];    // Q token-major, pre-scaled
__device__ __half g_kh[(size_t)B_ * N_ * C_];    // K token-major
__device__ __half g_vh[(size_t)B_ * N_ * C_];    // V token-major
__device__ __half g_oh[(size_t)B_ * N_ * C_];    // attention out, token-major
__device__ __half g_wqh[3 * C_ * C_];            // w_qkv fp16 [o][c]
__device__ __half g_woh[C_ * C_];                // w_out fp16 [o][c]
__device__ float  g_fs[B_ * C_];
__device__ float  g_fb[B_ * C_];

// ---------------------------------------------------------------------------
// Helpers
// ---------------------------------------------------------------------------
__device__ __forceinline__ void mma_f16(float* c,
    uint32_t a0, uint32_t a1, uint32_t a2, uint32_t a3,
    uint32_t b0, uint32_t b1)
{
    asm volatile(
        "mma.sync.aligned.m16n8k16.row.col.f32.f16.f16.f32 "
        "{%0,%1,%2,%3}, {%4,%5,%6,%7}, {%8,%9}, {%0,%1,%2,%3};"
        : "+f"(c[0]), "+f"(c[1]), "+f"(c[2]), "+f"(c[3])
        : "r"(a0), "r"(a1), "r"(a2), "r"(a3), "r"(b0), "r"(b1));
}
__device__ __forceinline__ void ldsm4(uint32_t& r0, uint32_t& r1,
                                      uint32_t& r2, uint32_t& r3, uint32_t addr)
{
    asm volatile("ldmatrix.sync.aligned.m8n8.x4.shared.b16 {%0,%1,%2,%3}, [%4];"
        : "=r"(r0), "=r"(r1), "=r"(r2), "=r"(r3) : "r"(addr));
}
__device__ __forceinline__ void ldsm4t(uint32_t& r0, uint32_t& r1,
                                       uint32_t& r2, uint32_t& r3, uint32_t addr)
{
    asm volatile("ldmatrix.sync.aligned.m8n8.x4.trans.shared.b16 {%0,%1,%2,%3}, [%4];"
        : "=r"(r0), "=r"(r1), "=r"(r2), "=r"(r3) : "r"(addr));
}
__device__ __forceinline__ float ex2f(float x) {
    float r;
    asm("ex2.approx.ftz.f32 %0, %1;" : "=f"(r) : "f"(x));
    return r;
}
__device__ __forceinline__ uint32_t fp2h2(float lo, float hi) {
    __half2 h = __floats2half2_rn(lo, hi);
    return *reinterpret_cast<uint32_t*>(&h);
}
__device__ __forceinline__ uint32_t smem_u32(const void* p) {
    uint32_t a;
    asm("{ .reg .u64 t; cvta.to.shared.u64 t, %1; cvt.u32.u64 %0, t; }"
        : "=r"(a) : "l"(p));
    return a;
}
__device__ __forceinline__ void cp16(uint32_t dst, const void* src) {
    asm volatile("cp.async.cg.shared.global [%0], [%1], 16;"
                 :: "r"(dst), "l"(src) : "memory");
}
#define CP_COMMIT() asm volatile("cp.async.commit_group;" ::: "memory")
#define CP_WAIT1()  asm volatile("cp.async.wait_group 1;" ::: "memory")
#define CP_WAIT0()  asm volatile("cp.async.wait_group 0;" ::: "memory")

// ---------------------------------------------------------------------------
// Kernel 1: GroupNorm stats -> fused per-(b,c) scale/bias
// ---------------------------------------------------------------------------
__global__ __launch_bounds__(256) void gn_stats_kernel(
    const float* __restrict__ x,
    const float* __restrict__ gamma,
    const float* __restrict__ beta)
{
    int b = blockIdx.x >> 3;
    int g = blockIdx.x & 7;
    const float4* p = reinterpret_cast<const float4*>(
        x + ((size_t)(b * C_ + g * CPG_)) * N_);
    float s1 = 0.f, s2 = 0.f;
    for (int i = threadIdx.x; i < 32768; i += 256) {
        float4 v = p[i];
        s1 += (v.x + v.y) + (v.z + v.w);
        s2 += (v.x * v.x + v.y * v.y) + (v.z * v.z + v.w * v.w);
    }
    #pragma unroll
    for (int off = 16; off; off >>= 1) {
        s1 += __shfl_xor_sync(0xffffffffu, s1, off);
        s2 += __shfl_xor_sync(0xffffffffu, s2, off);
    }
    __shared__ float a1[8], a2[8];
    __shared__ float sh_mean, sh_rstd;
    int warp = threadIdx.x >> 5;
    if ((threadIdx.x & 31) == 0) { a1[warp] = s1; a2[warp] = s2; }
    __syncthreads();
    if (threadIdx.x == 0) {
        float t1 = 0.f, t2 = 0.f;
        #pragma unroll
        for (int w = 0; w < 8; w++) { t1 += a1[w]; t2 += a2[w]; }
        float mean = t1 * (1.f / 131072.f);
        float var  = t2 * (1.f / 131072.f) - mean * mean;
        sh_mean = mean;
        sh_rstd = rsqrtf(var + EPS_);
    }
    __syncthreads();
    if (threadIdx.x < CPG_) {
        int c  = g * CPG_ + threadIdx.x;
        float ga = gamma[c];
        float fs = sh_rstd * ga;
        g_fs[b * C_ + c] = fs;
        g_fb[b * C_ + c] = beta[c] - sh_mean * fs;
    }
}

// ---------------------------------------------------------------------------
// Kernel 2a: weights fp32 -> fp16
// ---------------------------------------------------------------------------
__global__ __launch_bounds__(256) void wconv_kernel(
    const float* __restrict__ wq, const float* __restrict__ wo)
{
    int i = blockIdx.x * 256 + threadIdx.x;
    for (int k = i; k < 3 * C_ * C_; k += 65536)
        g_wqh[k] = __float2half(wq[k]);
    if (i < C_ * C_)
        g_woh[i] = __float2half(wo[i]);
}

// ---------------------------------------------------------------------------
// Kernel 2b: xn = GN(x) as fp16 token-major (B, N, C)
// ---------------------------------------------------------------------------
__global__ __launch_bounds__(256) void xn_half_kernel(const float* __restrict__ x)
{
    __shared__ float T[64][65];
    int n0 = blockIdx.x * 256;
    int c0 = blockIdx.y * 64;
    int b  = blockIdx.z;
    int tid = threadIdx.x;
    const float* fsb = g_fs + b * C_;
    const float* fbb = g_fb + b * C_;

    for (int s = 0; s < 4; s++) {
        int nn0 = n0 + s * 64;
        for (int idx = tid; idx < 1024; idx += 256) {
            int cc = idx >> 4, nn4 = (idx & 15) * 4;
            float4 v = *(const float4*)&x[((size_t)(b * C_ + c0 + cc)) * N_ + nn0 + nn4];
            float fs = fsb[c0 + cc], fb = fbb[c0 + cc];
            T[cc][nn4 + 0] = v.x * fs + fb;
            T[cc][nn4 + 1] = v.y * fs + fb;
            T[cc][nn4 + 2] = v.z * fs + fb;
            T[cc][nn4 + 3] = v.w * fs + fb;
        }
        __syncthreads();
        for (int idx = tid; idx < 2048; idx += 256) {
            int nn = idx >> 5, c = (idx & 31) * 2;
            *(uint32_t*)&g_xh[((size_t)b * N_ + nn0 + nn) * C_ + c0 + c] =
                fp2h2(T[c][nn], T[c + 1][nn]);
        }
        __syncthreads();
    }
}

// ---------------------------------------------------------------------------
// Kernel 3: QKV GEMM fp16 mma + ldmatrix. CTA = 128 tokens x 64 outputs.
// grid (N/128, 12, B); type = y>>2. All outputs token-major now.
// ---------------------------------------------------------------------------
#define AP 264
#define HG_SMEM ((128 * AP + 64 * AP) * 2)   // 101376 B

__global__ __launch_bounds__(256) void qkv_hgemm_kernel(
    const float* __restrict__ bias)
{
    extern __shared__ __align__(16) char smraw[];
    __half* Ah = (__half*)smraw;
    __half* Bh = Ah + 128 * AP;

    int tid = threadIdx.x;
    int w = tid >> 5, lid = tid & 31;
    int g = lid >> 2, t = lid & 3;
    int wrow = w * 16;
    int n0 = blockIdx.x * 128;
    int o0 = blockIdx.y * 64;
    int b  = blockIdx.z;

    const __half* ag = g_xh + ((size_t)b * N_ + n0) * C_;
    const __half* bg = g_wqh + (size_t)o0 * C_;
    for (int idx = tid; idx < 4096; idx += 256) {
        int r = idx >> 5, c8 = idx & 31;
        *(uint4*)(Ah + r * AP + c8 * 8) = *(const uint4*)(ag + (size_t)r * C_ + c8 * 8);
    }
    for (int idx = tid; idx < 2048; idx += 256) {
        int r = idx >> 5, c8 = idx & 31;
        *(uint4*)(Bh + r * AP + c8 * 8) = *(const uint4*)(bg + (size_t)r * C_ + c8 * 8);
    }
    __syncthreads();

    uint32_t aa = smem_u32(Ah) +
        (uint32_t)(((wrow + (lid & 15)) * AP + (lid >> 4) * 8) * 2);
    uint32_t bb = smem_u32(Bh) +
        (uint32_t)(((((lid & 7) + ((lid >> 4) & 1) * 8)) * AP + ((lid >> 3) & 1) * 8) * 2);

    float acc[8][4];
    #pragma unroll
    for (int nb = 0; nb < 8; nb++)
        #pragma unroll
        for (int j = 0; j < 4; j++) acc[nb][j] = 0.f;

    #pragma unroll 4
    for (int kk = 0; kk < 16; kk++) {
        uint32_t a0, a1, a2, a3;
        ldsm4(a0, a1, a2, a3, aa + kk * 32);
        #pragma unroll
        for (int nbp = 0; nbp < 4; nbp++) {
            uint32_t b0, b1, b2, b3;
            ldsm4(b0, b1, b2, b3, bb + (nbp * 16 * AP + kk * 16) * 2);
            mma_f16(acc[2 * nbp],     a0, a1, a2, a3, b0, b1);
            mma_f16(acc[2 * nbp + 1], a0, a1, a2, a3, b2, b3);
        }
    }

    int type = blockIdx.y >> 2;           // 0 Q, 1 K, 2 V
    int n_lo = n0 + wrow + g;
    float scale = (type == 0) ? QSCALE_ : 1.f;
    __half* gdst = (type == 0 ? g_qh : (type == 1 ? g_kh : g_vh));
    #pragma unroll
    for (int nb = 0; nb < 8; nb++) {
        int og = o0 + nb * 8 + 2 * t;
        int oo = og & 255;
        float b0v = bias[og], b1v = bias[og + 1];
        __half* dst = gdst + ((size_t)b * N_ + n_lo) * C_ + oo;
        *(uint32_t*)dst = fp2h2((acc[nb][0] + b0v) * scale, (acc[nb][1] + b1v) * scale);
        *(uint32_t*)(dst + 8 * C_) = fp2h2((acc[nb][2] + b0v) * scale, (acc[nb][3] + b1v) * scale);
    }
}

// ---------------------------------------------------------------------------
// Kernel 4: flash attention, 128 thr / 4 warps, 64 query rows/CTA,
// 2-stage cp.async ring, V token-major via ldmatrix.trans. 2 CTAs/SM.
// ---------------------------------------------------------------------------
#define QPH 264
#define KPH 264
#define VP2 264
#define PPH 40
#define QWH (64 * QPH)                  // 16896 halves
#define KWH (32 * KPH)                  // 8448
#define VWH (32 * VP2)                  // 8448
#define PWH (64 * PPH)                  // 2560
#define FL_SMEM ((QWH + 2 * KWH + 2 * VWH + PWH) * 2)   // 106496 B

__global__ void __launch_bounds__(128, 2) flash_kernel()
{
    extern __shared__ __align__(16) char smraw[];
    __half* Qh = (__half*)smraw;
    __half* Ph = Qh + QWH + 2 * KWH + 2 * VWH;
    uint32_t sb = smem_u32(smraw);
    uint32_t ka[2], va[2];
    #pragma unroll
    for (int s = 0; s < 2; s++) {
        ka[s] = sb + (QWH + s * KWH) * 2;
        va[s] = sb + (QWH + 2 * KWH + s * VWH) * 2;
    }
    uint32_t pa_base = sb + (uint32_t)((QWH + 2 * KWH + 2 * VWH) * 2);

    int tid = threadIdx.x;
    int w   = tid >> 5;
    int lid = tid & 31;
    int g   = lid >> 2;
    int t   = lid & 3;
    int b   = blockIdx.y;
    int n0  = blockIdx.x * 64;
    int wrow = w * 16;

    const __half* qg = g_qh + ((size_t)b * N_ + n0) * C_;
    const __half* kg = g_kh + (size_t)b * N_ * C_;
    const __half* vg = g_vh + (size_t)b * N_ * C_;

    // prologue: tiles 0 and 1 (each: K 1024 chunks + V 1024 chunks, 16B)
    #pragma unroll
    for (int j = 0; j < 2; j++) {
        for (int ch = tid; ch < 1024; ch += 128) {
            int r = ch >> 5, c8 = ch & 31;
            cp16(ka[j] + (r * KPH + c8 * 8) * 2,
                 kg + (size_t)(j * 32 + r) * C_ + c8 * 8);
            cp16(va[j] + (r * VP2 + c8 * 8) * 2,
                 vg + (size_t)(j * 32 + r) * C_ + c8 * 8);
        }
        CP_COMMIT();
    }

    // Q fill
    for (int idx = tid; idx < 2048; idx += 128) {
        int r = idx >> 5, c8 = idx & 31;
        *(uint4*)(Qh + r * QPH + c8 * 8) =
            *(const uint4*)(qg + (size_t)r * C_ + c8 * 8);
    }

    // ldmatrix lane addresses
    uint32_t qa = sb + (uint32_t)(((wrow + (lid & 15)) * QPH + (lid >> 4) * 8) * 2);
    uint32_t kbo = (uint32_t)(((((lid & 7) + ((lid >> 4) & 1) * 8)) * KPH
                               + ((lid >> 3) & 1) * 8) * 2);
    // V trans: lane -> k-row = (lid&7) + ((lid>>3)&1)*8, n-col-off = (lid>>4)*8
    uint32_t vbo = (uint32_t)((((lid & 7) + ((lid >> 3) & 1) * 8) * VP2
                               + (lid >> 4) * 8) * 2);
    uint32_t pra = pa_base + (uint32_t)(((wrow + (lid & 15)) * PPH + (lid >> 4) * 8) * 2);
    __half* pst = Ph + (wrow + g) * PPH + 2 * t;

    float Oacc[32][4];
    #pragma unroll
    for (int nb = 0; nb < 32; nb++)
        #pragma unroll
        for (int j = 0; j < 4; j++) Oacc[nb][j] = 0.f;
    float lsum_lo = 0.f, lsum_hi = 0.f;

    for (int i = 0; i < 128; i++) {
        if (i < 127) { CP_WAIT1(); } else { CP_WAIT0(); }
        __syncthreads();

        int bc = i & 1;
        uint32_t kbuf = ka[bc] + kbo;
        uint32_t vbuf = va[bc] + vbo;

        // ---- S = Q @ K^T : 16 rows x 32 keys, K=256
        float s[4][4];
        #pragma unroll
        for (int nb = 0; nb < 4; nb++)
            #pragma unroll
            for (int j = 0; j < 4; j++) s[nb][j] = 0.f;
        #pragma unroll 4
        for (int kk = 0; kk < 16; kk++) {
            uint32_t a0, a1, a2, a3;
            ldsm4(a0, a1, a2, a3, qa + kk * 32);
            #pragma unroll
            for (int nbp = 0; nbp < 2; nbp++) {
                uint32_t b0, b1, b2, b3;
                ldsm4(b0, b1, b2, b3, kbuf + (nbp * 16 * KPH + kk * 16) * 2);
                mma_f16(s[2 * nbp],     a0, a1, a2, a3, b0, b1);
                mma_f16(s[2 * nbp + 1], a0, a1, a2, a3, b2, b3);
            }
        }

        // ---- P = exp2(S)
        #pragma unroll
        for (int nb = 0; nb < 4; nb++) {
            float e0 = ex2f(s[nb][0]);
            float e1 = ex2f(s[nb][1]);
            float e2 = ex2f(s[nb][2]);
            float e3 = ex2f(s[nb][3]);
            lsum_lo += e0 + e1;
            lsum_hi += e2 + e3;
            *(uint32_t*)(pst + nb * 8)           = fp2h2(e0, e1);
            *(uint32_t*)(pst + 8 * PPH + nb * 8) = fp2h2(e2, e3);
        }
        __syncwarp();

        // ---- O += P @ V : 16 rows x 256 channels, K=32 (V via ldsm.trans)
        uint32_t pf[2][4];
        #pragma unroll
        for (int kst = 0; kst < 2; kst++)
            ldsm4(pf[kst][0], pf[kst][1], pf[kst][2], pf[kst][3], pra + kst * 32);
        #pragma unroll 4
        for (int nbp = 0; nbp < 16; nbp++) {
            #pragma unroll
            for (int kst = 0; kst < 2; kst++) {
                uint32_t b0, b1, b2, b3;
                // tile: k rows kst*16.., n cols nbp*16..
                ldsm4t(b0, b1, b2, b3, vbuf + (kst * 16 * VP2 + nbp * 16) * 2);
                mma_f16(Oacc[2 * nbp],     pf[kst][0], pf[kst][1], pf[kst][2], pf[kst][3], b0, b1);
                mma_f16(Oacc[2 * nbp + 1], pf[kst][0], pf[kst][1], pf[kst][2], pf[kst][3], b2, b3);
            }
        }

        // buffer-reuse guard, then prefetch tile i+2 into the buffer just freed
        __syncthreads();
        if (i < 126) {
            int j = i + 2;
            uint32_t kd = ka[bc], vd = va[bc];
            for (int ch = tid; ch < 1024; ch += 128) {
                int r = ch >> 5, c8 = ch & 31;
                cp16(kd + (r * KPH + c8 * 8) * 2,
                     kg + (size_t)(j * 32 + r) * C_ + c8 * 8);
                cp16(vd + (r * VP2 + c8 * 8) * 2,
                     vg + (size_t)(j * 32 + r) * C_ + c8 * 8);
            }
            CP_COMMIT();
        }
    }

    // row-sum reduce across the 4 col-group lanes
    lsum_lo += __shfl_xor_sync(0xffffffffu, lsum_lo, 1);
    lsum_lo += __shfl_xor_sync(0xffffffffu, lsum_lo, 2);
    lsum_hi += __shfl_xor_sync(0xffffffffu, lsum_hi, 1);
    lsum_hi += __shfl_xor_sync(0xffffffffu, lsum_hi, 2);
    float inv_lo = 1.f / lsum_lo;
    float inv_hi = 1.f / lsum_hi;

    // epilogue: fp16 O token-major
    __half* od = g_oh + ((size_t)b * N_ + n0 + wrow + g) * C_;
    #pragma unroll
    for (int nb = 0; nb < 32; nb++) {
        int c = nb * 8 + 2 * t;
        *(uint32_t*)(od + c) = fp2h2(Oacc[nb][0] * inv_lo, Oacc[nb][1] * inv_lo);
        *(uint32_t*)(od + 8 * C_ + c) = fp2h2(Oacc[nb][2] * inv_hi, Oacc[nb][3] * inv_hi);
    }
}

// ---------------------------------------------------------------------------
// Kernel 5: output projection fp16 mma + ldmatrix + bias + residual.
// CTA = 128 tokens x 64 outputs; grid (N/128, 4, B). 2 CTAs/SM.
// ---------------------------------------------------------------------------
__global__ __launch_bounds__(256) void proj_hgemm_kernel(
    const float* __restrict__ bias,
    const float* __restrict__ x,
    float* __restrict__ out)
{
    extern __shared__ __align__(16) char smraw[];
    __half* Ah = (__half*)smraw;
    __half* Bh = Ah + 128 * AP;
    float* Ts  = (float*)smraw;          // reused after compute: 64 x 136

    int tid = threadIdx.x;
    int w = tid >> 5, lid = tid & 31;
    int g = lid >> 2, t = lid & 3;
    int wrow = w * 16;
    int n0 = blockIdx.x * 128;
    int o0 = blockIdx.y * 64;
    int b  = blockIdx.z;

    const __half* ag = g_oh + ((size_t)b * N_ + n0) * C_;
    const __half* bg = g_woh + (size_t)o0 * C_;
    for (int idx = tid; idx < 4096; idx += 256) {
        int r = idx >> 5, c8 = idx & 31;
        *(uint4*)(Ah + r * AP + c8 * 8) = *(const uint4*)(ag + (size_t)r * C_ + c8 * 8);
    }
    for (int idx = tid; idx < 2048; idx += 256) {
        int r = idx >> 5, c8 = idx & 31;
        *(uint4*)(Bh + r * AP + c8 * 8) = *(const uint4*)(bg + (size_t)r * C_ + c8 * 8);
    }
    __syncthreads();

    uint32_t aa = smem_u32(Ah) +
        (uint32_t)(((wrow + (lid & 15)) * AP + (lid >> 4) * 8) * 2);
    uint32_t bb = smem_u32(Bh) +
        (uint32_t)(((((lid & 7) + ((lid >> 4) & 1) * 8)) * AP + ((lid >> 3) & 1) * 8) * 2);

    float acc[8][4];
    #pragma unroll
    for (int nb = 0; nb < 8; nb++)
        #pragma unroll
        for (int j = 0; j < 4; j++) acc[nb][j] = 0.f;

    #pragma unroll 4
    for (int kk = 0; kk < 16; kk++) {
        uint32_t a0, a1, a2, a3;
        ldsm4(a0, a1, a2, a3, aa + kk * 32);
        #pragma unroll
        for (int nbp = 0; nbp < 4; nbp++) {
            uint32_t b0, b1, b2, b3;
            ldsm4(b0, b1, b2, b3, bb + (nbp * 16 * AP + kk * 16) * 2);
            mma_f16(acc[2 * nbp],     a0, a1, a2, a3, b0, b1);
            mma_f16(acc[2 * nbp + 1], a0, a1, a2, a3, b2, b3);
        }
    }

    // stage D transposed [o_local][token] in fp32
    __syncthreads();
    #pragma unroll
    for (int nb = 0; nb < 8; nb++) {
        int ol = nb * 8 + 2 * t;
        Ts[ol * 136 + wrow + g]           = acc[nb][0];
        Ts[(ol + 1) * 136 + wrow + g]     = acc[nb][1];
        Ts[ol * 136 + wrow + g + 8]       = acc[nb][2];
        Ts[(ol + 1) * 136 + wrow + g + 8] = acc[nb][3];
    }
    __syncthreads();

    for (int idx = tid; idx < 2048; idx += 256) {
        int o = idx >> 5, n4 = (idx & 31) * 4;
        int og = o0 + o;
        float bo = bias[og];
        size_t base = ((size_t)b * C_ + og) * N_ + n0 + n4;
        float4 res = *(const float4*)&x[base];
        float4 d   = *(const float4*)&Ts[o * 136 + n4];
        float4 r = make_float4(d.x + bo + res.x, d.y + bo + res.y,
                               d.z + bo + res.z, d.w + bo + res.w);
        *(float4*)&out[base] = r;
    }
}

// ---------------------------------------------------------------------------
// Launch
// ---------------------------------------------------------------------------
extern "C" void kernel_launch(void* const* d_in, const int* in_sizes, int n_in,
                              void* d_out, int out_size)
{
    const float* x        = (const float*)d_in[0];
    const float* gn_scale = (const float*)d_in[1];
    const float* gn_bias  = (const float*)d_in[2];
    const float* w_qkv    = (const float*)d_in[3];
    const float* b_qkv    = (const float*)d_in[4];
    const float* w_out    = (const float*)d_in[5];
    const float* b_out    = (const float*)d_in[6];
    float* out = (float*)d_out;

    cudaFuncSetAttribute(flash_kernel,
                         cudaFuncAttributeMaxDynamicSharedMemorySize, FL_SMEM);
    cudaFuncSetAttribute(qkv_hgemm_kernel,
                         cudaFuncAttributeMaxDynamicSharedMemorySize, HG_SMEM);
    cudaFuncSetAttribute(proj_hgemm_kernel,
                         cudaFuncAttributeMaxDynamicSharedMemorySize, HG_SMEM);

    wconv_kernel<<<256, 256>>>(w_qkv, w_out);
    gn_stats_kernel<<<B_ * G_, 256>>>(x, gn_scale, gn_bias);
    xn_half_kernel<<<dim3(N_ / 256, C_ / 64, B_), 256>>>(x);
    qkv_hgemm_kernel<<<dim3(N_ / 128, 12, B_), 256, HG_SMEM>>>(b_qkv);
    flash_kernel<<<dim3(N_ / 64, B_), 128, FL_SMEM>>>();
    proj_hgemm_kernel<<<dim3(N_ / 128, 4, B_), 256, HG_SMEM>>>(b_out, x, out);
}

// round 12
// speedup vs baseline: 1.0504x; 1.0504x over previous
#include <cuda_runtime.h>
#include <cuda_fp16.h>
#include <cstdint>

// ---------------------------------------------------------------------------
// Problem constants
// ---------------------------------------------------------------------------
#define B_   8
#define C_   256
#define N_   4096
#define G_   8
#define CPG_ 32
#define EPS_ 1e-5f
#define QSCALE_ 0.09016844270216718f   // log2(e)/sqrt(C)

// ---------------------------------------------------------------------------
// Device scratch
// ---------------------------------------------------------------------------
__device__ __half g_xh[(size_t)B_ * N_ * C_];    // GN-applied x, token-major
__device__ __half g_qh[(size_t)B_ * N_ * C_];    // Q token-major, pre-scaled
__device__ __half g_kh[(size_t)B_ * N_ * C_];    // K token-major
__device__ __half g_vh[(size_t)B_ * N_ * C_];    // V token-major
__device__ __half g_oh[(size_t)B_ * N_ * C_];    // attention out, token-major
__device__ __half g_wqh[3 * C_ * C_];            // w_qkv fp16 [o][c]
__device__ __half g_woh[C_ * C_];                // w_out fp16 [o][c]
__device__ float  g_fs[B_ * C_];
__device__ float  g_fb[B_ * C_];

// ---------------------------------------------------------------------------
// Helpers
// ---------------------------------------------------------------------------
__device__ __forceinline__ void mma_f16(float* c,
    uint32_t a0, uint32_t a1, uint32_t a2, uint32_t a3,
    uint32_t b0, uint32_t b1)
{
    asm volatile(
        "mma.sync.aligned.m16n8k16.row.col.f32.f16.f16.f32 "
        "{%0,%1,%2,%3}, {%4,%5,%6,%7}, {%8,%9}, {%0,%1,%2,%3};"
        : "+f"(c[0]), "+f"(c[1]), "+f"(c[2]), "+f"(c[3])
        : "r"(a0), "r"(a1), "r"(a2), "r"(a3), "r"(b0), "r"(b1));
}
__device__ __forceinline__ void ldsm4(uint32_t& r0, uint32_t& r1,
                                      uint32_t& r2, uint32_t& r3, uint32_t addr)
{
    asm volatile("ldmatrix.sync.aligned.m8n8.x4.shared.b16 {%0,%1,%2,%3}, [%4];"
        : "=r"(r0), "=r"(r1), "=r"(r2), "=r"(r3) : "r"(addr));
}
__device__ __forceinline__ void ldsm4t(uint32_t& r0, uint32_t& r1,
                                       uint32_t& r2, uint32_t& r3, uint32_t addr)
{
    asm volatile("ldmatrix.sync.aligned.m8n8.x4.trans.shared.b16 {%0,%1,%2,%3}, [%4];"
        : "=r"(r0), "=r"(r1), "=r"(r2), "=r"(r3) : "r"(addr));
}
__device__ __forceinline__ float ex2f(float x) {
    float r;
    asm("ex2.approx.ftz.f32 %0, %1;" : "=f"(r) : "f"(x));
    return r;
}
__device__ __forceinline__ uint32_t fp2h2(float lo, float hi) {
    __half2 h = __floats2half2_rn(lo, hi);
    return *reinterpret_cast<uint32_t*>(&h);
}
__device__ __forceinline__ uint32_t smem_u32(const void* p) {
    uint32_t a;
    asm("{ .reg .u64 t; cvta.to.shared.u64 t, %1; cvt.u32.u64 %0, t; }"
        : "=r"(a) : "l"(p));
    return a;
}
__device__ __forceinline__ void cp16(uint32_t dst, const void* src) {
    asm volatile("cp.async.cg.shared.global [%0], [%1], 16;"
                 :: "r"(dst), "l"(src) : "memory");
}
#define CP_COMMIT() asm volatile("cp.async.commit_group;" ::: "memory")
#define CP_WAIT1()  asm volatile("cp.async.wait_group 1;" ::: "memory")
#define CP_WAIT0()  asm volatile("cp.async.wait_group 0;" ::: "memory")

// ---------------------------------------------------------------------------
// Kernel 1: GroupNorm stats -> fused per-(b,c) scale/bias
// ---------------------------------------------------------------------------
__global__ __launch_bounds__(256) void gn_stats_kernel(
    const float* __restrict__ x,
    const float* __restrict__ gamma,
    const float* __restrict__ beta)
{
    int b = blockIdx.x >> 3;
    int g = blockIdx.x & 7;
    const float4* p = reinterpret_cast<const float4*>(
        x + ((size_t)(b * C_ + g * CPG_)) * N_);
    float s1 = 0.f, s2 = 0.f;
    for (int i = threadIdx.x; i < 32768; i += 256) {
        float4 v = p[i];
        s1 += (v.x + v.y) + (v.z + v.w);
        s2 += (v.x * v.x + v.y * v.y) + (v.z * v.z + v.w * v.w);
    }
    #pragma unroll
    for (int off = 16; off; off >>= 1) {
        s1 += __shfl_xor_sync(0xffffffffu, s1, off);
        s2 += __shfl_xor_sync(0xffffffffu, s2, off);
    }
    __shared__ float a1[8], a2[8];
    __shared__ float sh_mean, sh_rstd;
    int warp = threadIdx.x >> 5;
    if ((threadIdx.x & 31) == 0) { a1[warp] = s1; a2[warp] = s2; }
    __syncthreads();
    if (threadIdx.x == 0) {
        float t1 = 0.f, t2 = 0.f;
        #pragma unroll
        for (int w = 0; w < 8; w++) { t1 += a1[w]; t2 += a2[w]; }
        float mean = t1 * (1.f / 131072.f);
        float var  = t2 * (1.f / 131072.f) - mean * mean;
        sh_mean = mean;
        sh_rstd = rsqrtf(var + EPS_);
    }
    __syncthreads();
    if (threadIdx.x < CPG_) {
        int c  = g * CPG_ + threadIdx.x;
        float ga = gamma[c];
        float fs = sh_rstd * ga;
        g_fs[b * C_ + c] = fs;
        g_fb[b * C_ + c] = beta[c] - sh_mean * fs;
    }
}

// ---------------------------------------------------------------------------
// Kernel 2a: weights fp32 -> fp16
// ---------------------------------------------------------------------------
__global__ __launch_bounds__(256) void wconv_kernel(
    const float* __restrict__ wq, const float* __restrict__ wo)
{
    int i = blockIdx.x * 256 + threadIdx.x;
    for (int k = i; k < 3 * C_ * C_; k += 65536)
        g_wqh[k] = __float2half(wq[k]);
    if (i < C_ * C_)
        g_woh[i] = __float2half(wo[i]);
}

// ---------------------------------------------------------------------------
// Kernel 2b: xn = GN(x) as fp16 token-major (B, N, C)
// ---------------------------------------------------------------------------
__global__ __launch_bounds__(256) void xn_half_kernel(const float* __restrict__ x)
{
    __shared__ float T[64][65];
    int n0 = blockIdx.x * 256;
    int c0 = blockIdx.y * 64;
    int b  = blockIdx.z;
    int tid = threadIdx.x;
    const float* fsb = g_fs + b * C_;
    const float* fbb = g_fb + b * C_;

    for (int s = 0; s < 4; s++) {
        int nn0 = n0 + s * 64;
        for (int idx = tid; idx < 1024; idx += 256) {
            int cc = idx >> 4, nn4 = (idx & 15) * 4;
            float4 v = *(const float4*)&x[((size_t)(b * C_ + c0 + cc)) * N_ + nn0 + nn4];
            float fs = fsb[c0 + cc], fb = fbb[c0 + cc];
            T[cc][nn4 + 0] = v.x * fs + fb;
            T[cc][nn4 + 1] = v.y * fs + fb;
            T[cc][nn4 + 2] = v.z * fs + fb;
            T[cc][nn4 + 3] = v.w * fs + fb;
        }
        __syncthreads();
        for (int idx = tid; idx < 2048; idx += 256) {
            int nn = idx >> 5, c = (idx & 31) * 2;
            *(uint32_t*)&g_xh[((size_t)b * N_ + nn0 + nn) * C_ + c0 + c] =
                fp2h2(T[c][nn], T[c + 1][nn]);
        }
        __syncthreads();
    }
}

// ---------------------------------------------------------------------------
// Kernel 3: QKV GEMM fp16 mma + ldmatrix. CTA = 128 tokens x 64 outputs.
// grid (N/128, 12, B); type = y>>2. All outputs token-major.
// ---------------------------------------------------------------------------
#define AP 264
#define HG_SMEM ((128 * AP + 64 * AP) * 2)   // 101376 B

__global__ __launch_bounds__(256) void qkv_hgemm_kernel(
    const float* __restrict__ bias)
{
    extern __shared__ __align__(16) char smraw[];
    __half* Ah = (__half*)smraw;
    __half* Bh = Ah + 128 * AP;

    int tid = threadIdx.x;
    int w = tid >> 5, lid = tid & 31;
    int g = lid >> 2, t = lid & 3;
    int wrow = w * 16;
    int n0 = blockIdx.x * 128;
    int o0 = blockIdx.y * 64;
    int b  = blockIdx.z;

    const __half* ag = g_xh + ((size_t)b * N_ + n0) * C_;
    const __half* bg = g_wqh + (size_t)o0 * C_;
    for (int idx = tid; idx < 4096; idx += 256) {
        int r = idx >> 5, c8 = idx & 31;
        *(uint4*)(Ah + r * AP + c8 * 8) = *(const uint4*)(ag + (size_t)r * C_ + c8 * 8);
    }
    for (int idx = tid; idx < 2048; idx += 256) {
        int r = idx >> 5, c8 = idx & 31;
        *(uint4*)(Bh + r * AP + c8 * 8) = *(const uint4*)(bg + (size_t)r * C_ + c8 * 8);
    }
    __syncthreads();

    uint32_t aa = smem_u32(Ah) +
        (uint32_t)(((wrow + (lid & 15)) * AP + (lid >> 4) * 8) * 2);
    uint32_t bb = smem_u32(Bh) +
        (uint32_t)(((((lid & 7) + ((lid >> 4) & 1) * 8)) * AP + ((lid >> 3) & 1) * 8) * 2);

    float acc[8][4];
    #pragma unroll
    for (int nb = 0; nb < 8; nb++)
        #pragma unroll
        for (int j = 0; j < 4; j++) acc[nb][j] = 0.f;

    #pragma unroll 4
    for (int kk = 0; kk < 16; kk++) {
        uint32_t a0, a1, a2, a3;
        ldsm4(a0, a1, a2, a3, aa + kk * 32);
        #pragma unroll
        for (int nbp = 0; nbp < 4; nbp++) {
            uint32_t b0, b1, b2, b3;
            ldsm4(b0, b1, b2, b3, bb + (nbp * 16 * AP + kk * 16) * 2);
            mma_f16(acc[2 * nbp],     a0, a1, a2, a3, b0, b1);
            mma_f16(acc[2 * nbp + 1], a0, a1, a2, a3, b2, b3);
        }
    }

    int type = blockIdx.y >> 2;           // 0 Q, 1 K, 2 V
    int n_lo = n0 + wrow + g;
    float scale = (type == 0) ? QSCALE_ : 1.f;
    __half* gdst = (type == 0 ? g_qh : (type == 1 ? g_kh : g_vh));
    #pragma unroll
    for (int nb = 0; nb < 8; nb++) {
        int og = o0 + nb * 8 + 2 * t;
        int oo = og & 255;
        float b0v = bias[og], b1v = bias[og + 1];
        __half* dst = gdst + ((size_t)b * N_ + n_lo) * C_ + oo;
        *(uint32_t*)dst = fp2h2((acc[nb][0] + b0v) * scale, (acc[nb][1] + b1v) * scale);
        *(uint32_t*)(dst + 8 * C_) = fp2h2((acc[nb][2] + b0v) * scale, (acc[nb][3] + b1v) * scale);
    }
}

// ---------------------------------------------------------------------------
// Kernel 4: flash attention, 256 thr / 8 warps, 128 query rows/CTA,
// 3-stage cp.async ring, register-resident P (S C-frag == PV A-frag),
// V token-major via ldmatrix.trans. No P smem, no syncwarp.
// ---------------------------------------------------------------------------
#define QPH 264
#define KPH 264
#define VP2 264
#define QWH (128 * QPH)                 // 33792 halves
#define KWH (32 * KPH)                  // 8448
#define VWH (32 * VP2)                  // 8448
#define FL_SMEM ((QWH + 3 * KWH + 3 * VWH) * 2)   // 168960 B

__global__ void __launch_bounds__(256, 1) flash_kernel()
{
    extern __shared__ __align__(16) char smraw[];
    __half* Qh = (__half*)smraw;
    uint32_t sb = smem_u32(smraw);
    uint32_t ka[3], va[3];
    #pragma unroll
    for (int s = 0; s < 3; s++) {
        ka[s] = sb + (QWH + s * KWH) * 2;
        va[s] = sb + (QWH + 3 * KWH + s * VWH) * 2;
    }

    int tid = threadIdx.x;
    int w   = tid >> 5;
    int lid = tid & 31;
    int b   = blockIdx.y;
    int n0  = blockIdx.x * 128;
    int wrow = w * 16;

    const __half* qg = g_qh + ((size_t)b * N_ + n0) * C_;
    const __half* kg = g_kh + (size_t)b * N_ * C_;
    const __half* vg = g_vh + (size_t)b * N_ * C_;

    // cp.async fill coords: K and V tiles are both 32 rows x 256 halves
    int kr = tid >> 5, kc8 = tid & 31;   // rows kr, kr+8, +16, +24

    // prologue: tiles 0 and 1
    #pragma unroll
    for (int j = 0; j < 2; j++) {
        #pragma unroll
        for (int rr = 0; rr < 32; rr += 8) {
            cp16(ka[j] + ((kr + rr) * KPH + kc8 * 8) * 2,
                 kg + (size_t)(j * 32 + kr + rr) * C_ + kc8 * 8);
            cp16(va[j] + ((kr + rr) * VP2 + kc8 * 8) * 2,
                 vg + (size_t)(j * 32 + kr + rr) * C_ + kc8 * 8);
        }
        CP_COMMIT();
    }

    // Q fill (overlaps prologue arrival)
    for (int idx = tid; idx < 4096; idx += 256) {
        int r = idx >> 5, c8 = idx & 31;
        *(uint4*)(Qh + r * QPH + c8 * 8) =
            *(const uint4*)(qg + (size_t)r * C_ + c8 * 8);
    }

    // ldmatrix lane addresses
    uint32_t qa = sb + (uint32_t)(((wrow + (lid & 15)) * QPH + (lid >> 4) * 8) * 2);
    uint32_t kbo = (uint32_t)(((((lid & 7) + ((lid >> 4) & 1) * 8)) * KPH
                               + ((lid >> 3) & 1) * 8) * 2);
    // V trans: row = key = (lid&7)+((lid>>3)&1)*8, col off = (lid>>4)*8
    uint32_t vbo = (uint32_t)((((lid & 7) + ((lid >> 3) & 1) * 8) * VP2
                               + (lid >> 4) * 8) * 2);

    float Oacc[32][4];
    #pragma unroll
    for (int nb = 0; nb < 32; nb++)
        #pragma unroll
        for (int j = 0; j < 4; j++) Oacc[nb][j] = 0.f;
    float lsum_lo = 0.f, lsum_hi = 0.f;

    int bc = 0, bw = 2;
    for (int i = 0; i < 128; i++) {
        if (i < 127) { CP_WAIT1(); } else { CP_WAIT0(); }
        __syncthreads();
        if (i < 126) {
            int j = i + 2;
            uint32_t kd = ka[bw], vd = va[bw];
            #pragma unroll
            for (int rr = 0; rr < 32; rr += 8) {
                cp16(kd + ((kr + rr) * KPH + kc8 * 8) * 2,
                     kg + (size_t)(j * 32 + kr + rr) * C_ + kc8 * 8);
                cp16(vd + ((kr + rr) * VP2 + kc8 * 8) * 2,
                     vg + (size_t)(j * 32 + kr + rr) * C_ + kc8 * 8);
            }
            CP_COMMIT();
        }

        uint32_t kbuf = ka[bc] + kbo;
        uint32_t vbuf = va[bc] + vbo;

        // ---- S = Q @ K^T : 16 rows x 32 keys, K=256
        float s[4][4];
        #pragma unroll
        for (int nb = 0; nb < 4; nb++)
            #pragma unroll
            for (int j = 0; j < 4; j++) s[nb][j] = 0.f;
        #pragma unroll 4
        for (int kk = 0; kk < 16; kk++) {
            uint32_t a0, a1, a2, a3;
            ldsm4(a0, a1, a2, a3, qa + kk * 32);
            #pragma unroll
            for (int nbp = 0; nbp < 2; nbp++) {
                uint32_t b0, b1, b2, b3;
                ldsm4(b0, b1, b2, b3, kbuf + (nbp * 16 * KPH + kk * 16) * 2);
                mma_f16(s[2 * nbp],     a0, a1, a2, a3, b0, b1);
                mma_f16(s[2 * nbp + 1], a0, a1, a2, a3, b2, b3);
            }
        }

        // ---- P = exp2(S) entirely in registers.
        // C-frag layout (row g: c0,c1 / row g+8: c2,c3) == A-frag layout of
        // the PV mma: kstep0 a0..a3 <- s[0],s[1]; kstep1 <- s[2],s[3].
        float e[4][4];
        #pragma unroll
        for (int nb = 0; nb < 4; nb++) {
            e[nb][0] = ex2f(s[nb][0]);
            e[nb][1] = ex2f(s[nb][1]);
            e[nb][2] = ex2f(s[nb][2]);
            e[nb][3] = ex2f(s[nb][3]);
            lsum_lo += e[nb][0] + e[nb][1];
            lsum_hi += e[nb][2] + e[nb][3];
        }
        uint32_t pf0[4] = { fp2h2(e[0][0], e[0][1]), fp2h2(e[0][2], e[0][3]),
                            fp2h2(e[1][0], e[1][1]), fp2h2(e[1][2], e[1][3]) };
        uint32_t pf1[4] = { fp2h2(e[2][0], e[2][1]), fp2h2(e[2][2], e[2][3]),
                            fp2h2(e[3][0], e[3][1]), fp2h2(e[3][2], e[3][3]) };

        // ---- O += P @ V : 16 rows x 256 channels, K=32 (V via ldsm.trans)
        #pragma unroll 4
        for (int nbp = 0; nbp < 16; nbp++) {
            uint32_t b0, b1, b2, b3;
            ldsm4t(b0, b1, b2, b3, vbuf + (nbp * 16) * 2);               // keys 0-15
            mma_f16(Oacc[2 * nbp],     pf0[0], pf0[1], pf0[2], pf0[3], b0, b1);
            mma_f16(Oacc[2 * nbp + 1], pf0[0], pf0[1], pf0[2], pf0[3], b2, b3);
            ldsm4t(b0, b1, b2, b3, vbuf + (16 * VP2 + nbp * 16) * 2);    // keys 16-31
            mma_f16(Oacc[2 * nbp],     pf1[0], pf1[1], pf1[2], pf1[3], b0, b1);
            mma_f16(Oacc[2 * nbp + 1], pf1[0], pf1[1], pf1[2], pf1[3], b2, b3);
        }

        bc = (bc == 2) ? 0 : bc + 1;
        bw = (bw == 2) ? 0 : bw + 1;
    }

    // row-sum reduce across the 4 col-group lanes
    lsum_lo += __shfl_xor_sync(0xffffffffu, lsum_lo, 1);
    lsum_lo += __shfl_xor_sync(0xffffffffu, lsum_lo, 2);
    lsum_hi += __shfl_xor_sync(0xffffffffu, lsum_hi, 1);
    lsum_hi += __shfl_xor_sync(0xffffffffu, lsum_hi, 2);
    float inv_lo = 1.f / lsum_lo;
    float inv_hi = 1.f / lsum_hi;

    // epilogue: fp16 O token-major
    int g = lid >> 2, t = lid & 3;
    __half* od = g_oh + ((size_t)b * N_ + n0 + wrow + g) * C_;
    #pragma unroll
    for (int nb = 0; nb < 32; nb++) {
        int c = nb * 8 + 2 * t;
        *(uint32_t*)(od + c) = fp2h2(Oacc[nb][0] * inv_lo, Oacc[nb][1] * inv_lo);
        *(uint32_t*)(od + 8 * C_ + c) = fp2h2(Oacc[nb][2] * inv_hi, Oacc[nb][3] * inv_hi);
    }
}

// ---------------------------------------------------------------------------
// Kernel 5: output projection fp16 mma + ldmatrix + bias + residual.
// CTA = 128 tokens x 64 outputs; grid (N/128, 4, B). 2 CTAs/SM.
// ---------------------------------------------------------------------------
__global__ __launch_bounds__(256) void proj_hgemm_kernel(
    const float* __restrict__ bias,
    const float* __restrict__ x,
    float* __restrict__ out)
{
    extern __shared__ __align__(16) char smraw[];
    __half* Ah = (__half*)smraw;
    __half* Bh = Ah + 128 * AP;
    float* Ts  = (float*)smraw;          // reused after compute: 64 x 136

    int tid = threadIdx.x;
    int w = tid >> 5, lid = tid & 31;
    int g = lid >> 2, t = lid & 3;
    int wrow = w * 16;
    int n0 = blockIdx.x * 128;
    int o0 = blockIdx.y * 64;
    int b  = blockIdx.z;

    const __half* ag = g_oh + ((size_t)b * N_ + n0) * C_;
    const __half* bg = g_woh + (size_t)o0 * C_;
    for (int idx = tid; idx < 4096; idx += 256) {
        int r = idx >> 5, c8 = idx & 31;
        *(uint4*)(Ah + r * AP + c8 * 8) = *(const uint4*)(ag + (size_t)r * C_ + c8 * 8);
    }
    for (int idx = tid; idx < 2048; idx += 256) {
        int r = idx >> 5, c8 = idx & 31;
        *(uint4*)(Bh + r * AP + c8 * 8) = *(const uint4*)(bg + (size_t)r * C_ + c8 * 8);
    }
    __syncthreads();

    uint32_t aa = smem_u32(Ah) +
        (uint32_t)(((wrow + (lid & 15)) * AP + (lid >> 4) * 8) * 2);
    uint32_t bb = smem_u32(Bh) +
        (uint32_t)(((((lid & 7) + ((lid >> 4) & 1) * 8)) * AP + ((lid >> 3) & 1) * 8) * 2);

    float acc[8][4];
    #pragma unroll
    for (int nb = 0; nb < 8; nb++)
        #pragma unroll
        for (int j = 0; j < 4; j++) acc[nb][j] = 0.f;

    #pragma unroll 4
    for (int kk = 0; kk < 16; kk++) {
        uint32_t a0, a1, a2, a3;
        ldsm4(a0, a1, a2, a3, aa + kk * 32);
        #pragma unroll
        for (int nbp = 0; nbp < 4; nbp++) {
            uint32_t b0, b1, b2, b3;
            ldsm4(b0, b1, b2, b3, bb + (nbp * 16 * AP + kk * 16) * 2);
            mma_f16(acc[2 * nbp],     a0, a1, a2, a3, b0, b1);
            mma_f16(acc[2 * nbp + 1], a0, a1, a2, a3, b2, b3);
        }
    }

    // stage D transposed [o_local][token] in fp32
    __syncthreads();
    #pragma unroll
    for (int nb = 0; nb < 8; nb++) {
        int ol = nb * 8 + 2 * t;
        Ts[ol * 136 + wrow + g]           = acc[nb][0];
        Ts[(ol + 1) * 136 + wrow + g]     = acc[nb][1];
        Ts[ol * 136 + wrow + g + 8]       = acc[nb][2];
        Ts[(ol + 1) * 136 + wrow + g + 8] = acc[nb][3];
    }
    __syncthreads();

    for (int idx = tid; idx < 2048; idx += 256) {
        int o = idx >> 5, n4 = (idx & 31) * 4;
        int og = o0 + o;
        float bo = bias[og];
        size_t base = ((size_t)b * C_ + og) * N_ + n0 + n4;
        float4 res = *(const float4*)&x[base];
        float4 d   = *(const float4*)&Ts[o * 136 + n4];
        float4 r = make_float4(d.x + bo + res.x, d.y + bo + res.y,
                               d.z + bo + res.z, d.w + bo + res.w);
        *(float4*)&out[base] = r;
    }
}

// ---------------------------------------------------------------------------
// Launch
// ---------------------------------------------------------------------------
extern "C" void kernel_launch(void* const* d_in, const int* in_sizes, int n_in,
                              void* d_out, int out_size)
{
    const float* x        = (const float*)d_in[0];
    const float* gn_scale = (const float*)d_in[1];
    const float* gn_bias  = (const float*)d_in[2];
    const float* w_qkv    = (const float*)d_in[3];
    const float* b_qkv    = (const float*)d_in[4];
    const float* w_out    = (const float*)d_in[5];
    const float* b_out    = (const float*)d_in[6];
    float* out = (float*)d_out;

    cudaFuncSetAttribute(flash_kernel,
                         cudaFuncAttributeMaxDynamicSharedMemorySize, FL_SMEM);
    cudaFuncSetAttribute(qkv_hgemm_kernel,
                         cudaFuncAttributeMaxDynamicSharedMemorySize, HG_SMEM);
    cudaFuncSetAttribute(proj_hgemm_kernel,
                         cudaFuncAttributeMaxDynamicSharedMemorySize, HG_SMEM);

    wconv_kernel<<<256, 256>>>(w_qkv, w_out);
    gn_stats_kernel<<<B_ * G_, 256>>>(x, gn_scale, gn_bias);
    xn_half_kernel<<<dim3(N_ / 256, C_ / 64, B_), 256>>>(x);
    qkv_hgemm_kernel<<<dim3(N_ / 128, 12, B_), 256, HG_SMEM>>>(b_qkv);
    flash_kernel<<<dim3(N_ / 128, B_), 256, FL_SMEM>>>();
    proj_hgemm_kernel<<<dim3(N_ / 128, 4, B_), 256, HG_SMEM>>>(b_out, x, out);
}

// round 13
// speedup vs baseline: 1.0585x; 1.0077x over previous
#include <cuda_runtime.h>
#include <cuda_fp16.h>
#include <cstdint>

// ---------------------------------------------------------------------------
// Problem constants
// ---------------------------------------------------------------------------
#define B_   8
#define C_   256
#define N_   4096
#define G_   8
#define CPG_ 32
#define EPS_ 1e-5f
#define QSCALE_ 0.09016844270216718f   // log2(e)/sqrt(C)

// ---------------------------------------------------------------------------
// Device scratch
// ---------------------------------------------------------------------------
__device__ __half g_xh[(size_t)B_ * N_ * C_];    // GN-applied x, token-major
__device__ __half g_qh[(size_t)B_ * N_ * C_];    // Q token-major, pre-scaled
__device__ __half g_kh[(size_t)B_ * N_ * C_];    // K token-major
__device__ __half g_vh[(size_t)B_ * N_ * C_];    // V token-major
__device__ __half g_oh[(size_t)B_ * N_ * C_];    // attention out, token-major
__device__ __half g_wqh[3 * C_ * C_];            // w_qkv fp16 [o][c]
__device__ __half g_woh[C_ * C_];                // w_out fp16 [o][c]
__device__ float  g_fs[B_ * C_];
__device__ float  g_fb[B_ * C_];

// ---------------------------------------------------------------------------
// Helpers
// ---------------------------------------------------------------------------
__device__ __forceinline__ void mma_f16(float* c,
    uint32_t a0, uint32_t a1, uint32_t a2, uint32_t a3,
    uint32_t b0, uint32_t b1)
{
    asm volatile(
        "mma.sync.aligned.m16n8k16.row.col.f32.f16.f16.f32 "
        "{%0,%1,%2,%3}, {%4,%5,%6,%7}, {%8,%9}, {%0,%1,%2,%3};"
        : "+f"(c[0]), "+f"(c[1]), "+f"(c[2]), "+f"(c[3])
        : "r"(a0), "r"(a1), "r"(a2), "r"(a3), "r"(b0), "r"(b1));
}
__device__ __forceinline__ void ldsm4(uint32_t& r0, uint32_t& r1,
                                      uint32_t& r2, uint32_t& r3, uint32_t addr)
{
    asm volatile("ldmatrix.sync.aligned.m8n8.x4.shared.b16 {%0,%1,%2,%3}, [%4];"
        : "=r"(r0), "=r"(r1), "=r"(r2), "=r"(r3) : "r"(addr));
}
__device__ __forceinline__ void ldsm4t(uint32_t& r0, uint32_t& r1,
                                       uint32_t& r2, uint32_t& r3, uint32_t addr)
{
    asm volatile("ldmatrix.sync.aligned.m8n8.x4.trans.shared.b16 {%0,%1,%2,%3}, [%4];"
        : "=r"(r0), "=r"(r1), "=r"(r2), "=r"(r3) : "r"(addr));
}
__device__ __forceinline__ float ex2f(float x) {
    float r;
    asm("ex2.approx.ftz.f32 %0, %1;" : "=f"(r) : "f"(x));
    return r;
}
__device__ __forceinline__ uint32_t fp2h2(float lo, float hi) {
    __half2 h = __floats2half2_rn(lo, hi);
    return *reinterpret_cast<uint32_t*>(&h);
}
__device__ __forceinline__ uint32_t smem_u32(const void* p) {
    uint32_t a;
    asm("{ .reg .u64 t; cvta.to.shared.u64 t, %1; cvt.u32.u64 %0, t; }"
        : "=r"(a) : "l"(p));
    return a;
}
__device__ __forceinline__ void cp16(uint32_t dst, const void* src) {
    asm volatile("cp.async.cg.shared.global [%0], [%1], 16;"
                 :: "r"(dst), "l"(src) : "memory");
}
#define CP_COMMIT() asm volatile("cp.async.commit_group;" ::: "memory")
#define CP_WAIT1()  asm volatile("cp.async.wait_group 1;" ::: "memory")
#define CP_WAIT0()  asm volatile("cp.async.wait_group 0;" ::: "memory")

// ---------------------------------------------------------------------------
// Kernel 1: GroupNorm stats -> fused per-(b,c) scale/bias
// ---------------------------------------------------------------------------
__global__ __launch_bounds__(256) void gn_stats_kernel(
    const float* __restrict__ x,
    const float* __restrict__ gamma,
    const float* __restrict__ beta)
{
    int b = blockIdx.x >> 3;
    int g = blockIdx.x & 7;
    const float4* p = reinterpret_cast<const float4*>(
        x + ((size_t)(b * C_ + g * CPG_)) * N_);
    float s1 = 0.f, s2 = 0.f;
    for (int i = threadIdx.x; i < 32768; i += 256) {
        float4 v = p[i];
        s1 += (v.x + v.y) + (v.z + v.w);
        s2 += (v.x * v.x + v.y * v.y) + (v.z * v.z + v.w * v.w);
    }
    #pragma unroll
    for (int off = 16; off; off >>= 1) {
        s1 += __shfl_xor_sync(0xffffffffu, s1, off);
        s2 += __shfl_xor_sync(0xffffffffu, s2, off);
    }
    __shared__ float a1[8], a2[8];
    __shared__ float sh_mean, sh_rstd;
    int warp = threadIdx.x >> 5;
    if ((threadIdx.x & 31) == 0) { a1[warp] = s1; a2[warp] = s2; }
    __syncthreads();
    if (threadIdx.x == 0) {
        float t1 = 0.f, t2 = 0.f;
        #pragma unroll
        for (int w = 0; w < 8; w++) { t1 += a1[w]; t2 += a2[w]; }
        float mean = t1 * (1.f / 131072.f);
        float var  = t2 * (1.f / 131072.f) - mean * mean;
        sh_mean = mean;
        sh_rstd = rsqrtf(var + EPS_);
    }
    __syncthreads();
    if (threadIdx.x < CPG_) {
        int c  = g * CPG_ + threadIdx.x;
        float ga = gamma[c];
        float fs = sh_rstd * ga;
        g_fs[b * C_ + c] = fs;
        g_fb[b * C_ + c] = beta[c] - sh_mean * fs;
    }
}

// ---------------------------------------------------------------------------
// Kernel 2a: weights fp32 -> fp16
// ---------------------------------------------------------------------------
__global__ __launch_bounds__(256) void wconv_kernel(
    const float* __restrict__ wq, const float* __restrict__ wo)
{
    int i = blockIdx.x * 256 + threadIdx.x;
    for (int k = i; k < 3 * C_ * C_; k += 65536)
        g_wqh[k] = __float2half(wq[k]);
    if (i < C_ * C_)
        g_woh[i] = __float2half(wo[i]);
}

// ---------------------------------------------------------------------------
// Kernel 2b: xn = GN(x) as fp16 token-major (B, N, C)
// ---------------------------------------------------------------------------
__global__ __launch_bounds__(256) void xn_half_kernel(const float* __restrict__ x)
{
    __shared__ float T[64][65];
    int n0 = blockIdx.x * 256;
    int c0 = blockIdx.y * 64;
    int b  = blockIdx.z;
    int tid = threadIdx.x;
    const float* fsb = g_fs + b * C_;
    const float* fbb = g_fb + b * C_;

    for (int s = 0; s < 4; s++) {
        int nn0 = n0 + s * 64;
        for (int idx = tid; idx < 1024; idx += 256) {
            int cc = idx >> 4, nn4 = (idx & 15) * 4;
            float4 v = *(const float4*)&x[((size_t)(b * C_ + c0 + cc)) * N_ + nn0 + nn4];
            float fs = fsb[c0 + cc], fb = fbb[c0 + cc];
            T[cc][nn4 + 0] = v.x * fs + fb;
            T[cc][nn4 + 1] = v.y * fs + fb;
            T[cc][nn4 + 2] = v.z * fs + fb;
            T[cc][nn4 + 3] = v.w * fs + fb;
        }
        __syncthreads();
        for (int idx = tid; idx < 2048; idx += 256) {
            int nn = idx >> 5, c = (idx & 31) * 2;
            *(uint32_t*)&g_xh[((size_t)b * N_ + nn0 + nn) * C_ + c0 + c] =
                fp2h2(T[c][nn], T[c + 1][nn]);
        }
        __syncthreads();
    }
}

// ---------------------------------------------------------------------------
// Kernel 3: QKV GEMM fp16 mma + ldmatrix. CTA = 128 tokens x 64 outputs.
// grid (N/128, 12, B); type = y>>2. All outputs token-major.
// ---------------------------------------------------------------------------
#define AP 264
#define HG_SMEM ((128 * AP + 64 * AP) * 2)   // 101376 B

__global__ __launch_bounds__(256) void qkv_hgemm_kernel(
    const float* __restrict__ bias)
{
    extern __shared__ __align__(16) char smraw[];
    __half* Ah = (__half*)smraw;
    __half* Bh = Ah + 128 * AP;

    int tid = threadIdx.x;
    int w = tid >> 5, lid = tid & 31;
    int g = lid >> 2, t = lid & 3;
    int wrow = w * 16;
    int n0 = blockIdx.x * 128;
    int o0 = blockIdx.y * 64;
    int b  = blockIdx.z;

    const __half* ag = g_xh + ((size_t)b * N_ + n0) * C_;
    const __half* bg = g_wqh + (size_t)o0 * C_;
    for (int idx = tid; idx < 4096; idx += 256) {
        int r = idx >> 5, c8 = idx & 31;
        *(uint4*)(Ah + r * AP + c8 * 8) = *(const uint4*)(ag + (size_t)r * C_ + c8 * 8);
    }
    for (int idx = tid; idx < 2048; idx += 256) {
        int r = idx >> 5, c8 = idx & 31;
        *(uint4*)(Bh + r * AP + c8 * 8) = *(const uint4*)(bg + (size_t)r * C_ + c8 * 8);
    }
    __syncthreads();

    uint32_t aa = smem_u32(Ah) +
        (uint32_t)(((wrow + (lid & 15)) * AP + (lid >> 4) * 8) * 2);
    uint32_t bb = smem_u32(Bh) +
        (uint32_t)(((((lid & 7) + ((lid >> 4) & 1) * 8)) * AP + ((lid >> 3) & 1) * 8) * 2);

    float acc[8][4];
    #pragma unroll
    for (int nb = 0; nb < 8; nb++)
        #pragma unroll
        for (int j = 0; j < 4; j++) acc[nb][j] = 0.f;

    #pragma unroll 4
    for (int kk = 0; kk < 16; kk++) {
        uint32_t a0, a1, a2, a3;
        ldsm4(a0, a1, a2, a3, aa + kk * 32);
        #pragma unroll
        for (int nbp = 0; nbp < 4; nbp++) {
            uint32_t b0, b1, b2, b3;
            ldsm4(b0, b1, b2, b3, bb + (nbp * 16 * AP + kk * 16) * 2);
            mma_f16(acc[2 * nbp],     a0, a1, a2, a3, b0, b1);
            mma_f16(acc[2 * nbp + 1], a0, a1, a2, a3, b2, b3);
        }
    }

    int type = blockIdx.y >> 2;           // 0 Q, 1 K, 2 V
    int n_lo = n0 + wrow + g;
    float scale = (type == 0) ? QSCALE_ : 1.f;
    __half* gdst = (type == 0 ? g_qh : (type == 1 ? g_kh : g_vh));
    #pragma unroll
    for (int nb = 0; nb < 8; nb++) {
        int og = o0 + nb * 8 + 2 * t;
        int oo = og & 255;
        float b0v = bias[og], b1v = bias[og + 1];
        __half* dst = gdst + ((size_t)b * N_ + n_lo) * C_ + oo;
        *(uint32_t*)dst = fp2h2((acc[nb][0] + b0v) * scale, (acc[nb][1] + b1v) * scale);
        *(uint32_t*)(dst + 8 * C_) = fp2h2((acc[nb][2] + b0v) * scale, (acc[nb][3] + b1v) * scale);
    }
}

// ---------------------------------------------------------------------------
// Kernel 4: flash attention, 256 thr / 8 warps, 128 query rows/CTA,
// 3-stage cp.async ring, register-resident P, V token-major via ldsm.trans,
// Q k-steps 0..7 hoisted into registers (loop-invariant).
// ---------------------------------------------------------------------------
#define QPH 264
#define KPH 264
#define VP2 264
#define QWH (128 * QPH)                 // 33792 halves
#define KWH (32 * KPH)                  // 8448
#define VWH (32 * VP2)                  // 8448
#define FL_SMEM ((QWH + 3 * KWH + 3 * VWH) * 2)   // 168960 B

__global__ void __launch_bounds__(256, 1) flash_kernel()
{
    extern __shared__ __align__(16) char smraw[];
    __half* Qh = (__half*)smraw;
    uint32_t sb = smem_u32(smraw);
    uint32_t ka[3], va[3];
    #pragma unroll
    for (int s = 0; s < 3; s++) {
        ka[s] = sb + (QWH + s * KWH) * 2;
        va[s] = sb + (QWH + 3 * KWH + s * VWH) * 2;
    }

    int tid = threadIdx.x;
    int w   = tid >> 5;
    int lid = tid & 31;
    int b   = blockIdx.y;
    int n0  = blockIdx.x * 128;
    int wrow = w * 16;

    const __half* qg = g_qh + ((size_t)b * N_ + n0) * C_;
    const __half* kg = g_kh + (size_t)b * N_ * C_;
    const __half* vg = g_vh + (size_t)b * N_ * C_;

    // cp.async fill coords: K and V tiles are both 32 rows x 256 halves
    int kr = tid >> 5, kc8 = tid & 31;   // rows kr, kr+8, +16, +24

    // prologue: tiles 0 and 1
    #pragma unroll
    for (int j = 0; j < 2; j++) {
        #pragma unroll
        for (int rr = 0; rr < 32; rr += 8) {
            cp16(ka[j] + ((kr + rr) * KPH + kc8 * 8) * 2,
                 kg + (size_t)(j * 32 + kr + rr) * C_ + kc8 * 8);
            cp16(va[j] + ((kr + rr) * VP2 + kc8 * 8) * 2,
                 vg + (size_t)(j * 32 + kr + rr) * C_ + kc8 * 8);
        }
        CP_COMMIT();
    }

    // Q fill (overlaps prologue arrival)
    for (int idx = tid; idx < 4096; idx += 256) {
        int r = idx >> 5, c8 = idx & 31;
        *(uint4*)(Qh + r * QPH + c8 * 8) =
            *(const uint4*)(qg + (size_t)r * C_ + c8 * 8);
    }
    __syncthreads();                     // Q visible for fragment preload

    // ldmatrix lane addresses
    uint32_t qa = sb + (uint32_t)(((wrow + (lid & 15)) * QPH + (lid >> 4) * 8) * 2);
    uint32_t kbo = (uint32_t)(((((lid & 7) + ((lid >> 4) & 1) * 8)) * KPH
                               + ((lid >> 3) & 1) * 8) * 2);
    uint32_t vbo = (uint32_t)((((lid & 7) + ((lid >> 3) & 1) * 8) * VP2
                               + (lid >> 4) * 8) * 2);

    // hoist Q k-steps 0..7 (channels 0..127) into registers: loop-invariant
    uint32_t qf[8][4];
    #pragma unroll
    for (int kk = 0; kk < 8; kk++)
        ldsm4(qf[kk][0], qf[kk][1], qf[kk][2], qf[kk][3], qa + kk * 32);

    float Oacc[32][4];
    #pragma unroll
    for (int nb = 0; nb < 32; nb++)
        #pragma unroll
        for (int j = 0; j < 4; j++) Oacc[nb][j] = 0.f;
    float lsum_lo = 0.f, lsum_hi = 0.f;

    int bc = 0, bw = 2;
    for (int i = 0; i < 128; i++) {
        if (i < 127) { CP_WAIT1(); } else { CP_WAIT0(); }
        __syncthreads();
        if (i < 126) {
            int j = i + 2;
            uint32_t kd = ka[bw], vd = va[bw];
            #pragma unroll
            for (int rr = 0; rr < 32; rr += 8) {
                cp16(kd + ((kr + rr) * KPH + kc8 * 8) * 2,
                     kg + (size_t)(j * 32 + kr + rr) * C_ + kc8 * 8);
                cp16(vd + ((kr + rr) * VP2 + kc8 * 8) * 2,
                     vg + (size_t)(j * 32 + kr + rr) * C_ + kc8 * 8);
            }
            CP_COMMIT();
        }

        uint32_t kbuf = ka[bc] + kbo;
        uint32_t vbuf = va[bc] + vbo;

        // ---- S = Q @ K^T : 16 rows x 32 keys, K=256
        float s[4][4];
        #pragma unroll
        for (int nb = 0; nb < 4; nb++)
            #pragma unroll
            for (int j = 0; j < 4; j++) s[nb][j] = 0.f;
        // k-steps 0..7 : A from registers, only K ldsm on the chain
        #pragma unroll
        for (int kk = 0; kk < 8; kk++) {
            #pragma unroll
            for (int nbp = 0; nbp < 2; nbp++) {
                uint32_t b0, b1, b2, b3;
                ldsm4(b0, b1, b2, b3, kbuf + (nbp * 16 * KPH + kk * 16) * 2);
                mma_f16(s[2 * nbp],     qf[kk][0], qf[kk][1], qf[kk][2], qf[kk][3], b0, b1);
                mma_f16(s[2 * nbp + 1], qf[kk][0], qf[kk][1], qf[kk][2], qf[kk][3], b2, b3);
            }
        }
        // k-steps 8..15 : A via ldsm
        #pragma unroll
        for (int kk = 8; kk < 16; kk++) {
            uint32_t a0, a1, a2, a3;
            ldsm4(a0, a1, a2, a3, qa + kk * 32);
            #pragma unroll
            for (int nbp = 0; nbp < 2; nbp++) {
                uint32_t b0, b1, b2, b3;
                ldsm4(b0, b1, b2, b3, kbuf + (nbp * 16 * KPH + kk * 16) * 2);
                mma_f16(s[2 * nbp],     a0, a1, a2, a3, b0, b1);
                mma_f16(s[2 * nbp + 1], a0, a1, a2, a3, b2, b3);
            }
        }

        // ---- P = exp2(S) entirely in registers (C-frag == PV A-frag)
        float e[4][4];
        #pragma unroll
        for (int nb = 0; nb < 4; nb++) {
            e[nb][0] = ex2f(s[nb][0]);
            e[nb][1] = ex2f(s[nb][1]);
            e[nb][2] = ex2f(s[nb][2]);
            e[nb][3] = ex2f(s[nb][3]);
            lsum_lo += e[nb][0] + e[nb][1];
            lsum_hi += e[nb][2] + e[nb][3];
        }
        uint32_t pf0[4] = { fp2h2(e[0][0], e[0][1]), fp2h2(e[0][2], e[0][3]),
                            fp2h2(e[1][0], e[1][1]), fp2h2(e[1][2], e[1][3]) };
        uint32_t pf1[4] = { fp2h2(e[2][0], e[2][1]), fp2h2(e[2][2], e[2][3]),
                            fp2h2(e[3][0], e[3][1]), fp2h2(e[3][2], e[3][3]) };

        // ---- O += P @ V : 16 rows x 256 channels, K=32 (V via ldsm.trans)
        #pragma unroll 4
        for (int nbp = 0; nbp < 16; nbp++) {
            uint32_t b0, b1, b2, b3;
            ldsm4t(b0, b1, b2, b3, vbuf + (nbp * 16) * 2);               // keys 0-15
            mma_f16(Oacc[2 * nbp],     pf0[0], pf0[1], pf0[2], pf0[3], b0, b1);
            mma_f16(Oacc[2 * nbp + 1], pf0[0], pf0[1], pf0[2], pf0[3], b2, b3);
            ldsm4t(b0, b1, b2, b3, vbuf + (16 * VP2 + nbp * 16) * 2);    // keys 16-31
            mma_f16(Oacc[2 * nbp],     pf1[0], pf1[1], pf1[2], pf1[3], b0, b1);
            mma_f16(Oacc[2 * nbp + 1], pf1[0], pf1[1], pf1[2], pf1[3], b2, b3);
        }

        bc = (bc == 2) ? 0 : bc + 1;
        bw = (bw == 2) ? 0 : bw + 1;
    }

    // row-sum reduce across the 4 col-group lanes
    lsum_lo += __shfl_xor_sync(0xffffffffu, lsum_lo, 1);
    lsum_lo += __shfl_xor_sync(0xffffffffu, lsum_lo, 2);
    lsum_hi += __shfl_xor_sync(0xffffffffu, lsum_hi, 1);
    lsum_hi += __shfl_xor_sync(0xffffffffu, lsum_hi, 2);
    float inv_lo = 1.f / lsum_lo;
    float inv_hi = 1.f / lsum_hi;

    // epilogue: fp16 O token-major
    int g = lid >> 2, t = lid & 3;
    __half* od = g_oh + ((size_t)b * N_ + n0 + wrow + g) * C_;
    #pragma unroll
    for (int nb = 0; nb < 32; nb++) {
        int c = nb * 8 + 2 * t;
        *(uint32_t*)(od + c) = fp2h2(Oacc[nb][0] * inv_lo, Oacc[nb][1] * inv_lo);
        *(uint32_t*)(od + 8 * C_ + c) = fp2h2(Oacc[nb][2] * inv_hi, Oacc[nb][3] * inv_hi);
    }
}

// ---------------------------------------------------------------------------
// Kernel 5: output projection fp16 mma + ldmatrix + bias + residual.
// CTA = 128 tokens x 64 outputs; grid (N/128, 4, B). 2 CTAs/SM.
// ---------------------------------------------------------------------------
__global__ __launch_bounds__(256) void proj_hgemm_kernel(
    const float* __restrict__ bias,
    const float* __restrict__ x,
    float* __restrict__ out)
{
    extern __shared__ __align__(16) char smraw[];
    __half* Ah = (__half*)smraw;
    __half* Bh = Ah + 128 * AP;
    float* Ts  = (float*)smraw;          // reused after compute: 64 x 136

    int tid = threadIdx.x;
    int w = tid >> 5, lid = tid & 31;
    int g = lid >> 2, t = lid & 3;
    int wrow = w * 16;
    int n0 = blockIdx.x * 128;
    int o0 = blockIdx.y * 64;
    int b  = blockIdx.z;

    const __half* ag = g_oh + ((size_t)b * N_ + n0) * C_;
    const __half* bg = g_woh + (size_t)o0 * C_;
    for (int idx = tid; idx < 4096; idx += 256) {
        int r = idx >> 5, c8 = idx & 31;
        *(uint4*)(Ah + r * AP + c8 * 8) = *(const uint4*)(ag + (size_t)r * C_ + c8 * 8);
    }
    for (int idx = tid; idx < 2048; idx += 256) {
        int r = idx >> 5, c8 = idx & 31;
        *(uint4*)(Bh + r * AP + c8 * 8) = *(const uint4*)(bg + (size_t)r * C_ + c8 * 8);
    }
    __syncthreads();

    uint32_t aa = smem_u32(Ah) +
        (uint32_t)(((wrow + (lid & 15)) * AP + (lid >> 4) * 8) * 2);
    uint32_t bb = smem_u32(Bh) +
        (uint32_t)(((((lid & 7) + ((lid >> 4) & 1) * 8)) * AP + ((lid >> 3) & 1) * 8) * 2);

    float acc[8][4];
    #pragma unroll
    for (int nb = 0; nb < 8; nb++)
        #pragma unroll
        for (int j = 0; j < 4; j++) acc[nb][j] = 0.f;

    #pragma unroll 4
    for (int kk = 0; kk < 16; kk++) {
        uint32_t a0, a1, a2, a3;
        ldsm4(a0, a1, a2, a3, aa + kk * 32);
        #pragma unroll
        for (int nbp = 0; nbp < 4; nbp++) {
            uint32_t b0, b1, b2, b3;
            ldsm4(b0, b1, b2, b3, bb + (nbp * 16 * AP + kk * 16) * 2);
            mma_f16(acc[2 * nbp],     a0, a1, a2, a3, b0, b1);
            mma_f16(acc[2 * nbp + 1], a0, a1, a2, a3, b2, b3);
        }
    }

    // stage D transposed [o_local][token] in fp32
    __syncthreads();
    #pragma unroll
    for (int nb = 0; nb < 8; nb++) {
        int ol = nb * 8 + 2 * t;
        Ts[ol * 136 + wrow + g]           = acc[nb][0];
        Ts[(ol + 1) * 136 + wrow + g]     = acc[nb][1];
        Ts[ol * 136 + wrow + g + 8]       = acc[nb][2];
        Ts[(ol + 1) * 136 + wrow + g + 8] = acc[nb][3];
    }
    __syncthreads();

    for (int idx = tid; idx < 2048; idx += 256) {
        int o = idx >> 5, n4 = (idx & 31) * 4;
        int og = o0 + o;
        float bo = bias[og];
        size_t base = ((size_t)b * C_ + og) * N_ + n0 + n4;
        float4 res = *(const float4*)&x[base];
        float4 d   = *(const float4*)&Ts[o * 136 + n4];
        float4 r = make_float4(d.x + bo + res.x, d.y + bo + res.y,
                               d.z + bo + res.z, d.w + bo + res.w);
        *(float4*)&out[base] = r;
    }
}

// ---------------------------------------------------------------------------
// Launch
// ---------------------------------------------------------------------------
extern "C" void kernel_launch(void* const* d_in, const int* in_sizes, int n_in,
                              void* d_out, int out_size)
{
    const float* x        = (const float*)d_in[0];
    const float* gn_scale = (const float*)d_in[1];
    const float* gn_bias  = (const float*)d_in[2];
    const float* w_qkv    = (const float*)d_in[3];
    const float* b_qkv    = (const float*)d_in[4];
    const float* w_out    = (const float*)d_in[5];
    const float* b_out    = (const float*)d_in[6];
    float* out = (float*)d_out;

    cudaFuncSetAttribute(flash_kernel,
                         cudaFuncAttributeMaxDynamicSharedMemorySize, FL_SMEM);
    cudaFuncSetAttribute(qkv_hgemm_kernel,
                         cudaFuncAttributeMaxDynamicSharedMemorySize, HG_SMEM);
    cudaFuncSetAttribute(proj_hgemm_kernel,
                         cudaFuncAttributeMaxDynamicSharedMemorySize, HG_SMEM);

    wconv_kernel<<<256, 256>>>(w_qkv, w_out);
    gn_stats_kernel<<<B_ * G_, 256>>>(x, gn_scale, gn_bias);
    xn_half_kernel<<<dim3(N_ / 256, C_ / 64, B_), 256>>>(x);
    qkv_hgemm_kernel<<<dim3(N_ / 128, 12, B_), 256, HG_SMEM>>>(b_qkv);
    flash_kernel<<<dim3(N_ / 128, B_), 256, FL_SMEM>>>();
    proj_hgemm_kernel<<<dim3(N_ / 128, 4, B_), 256, HG_SMEM>>>(b_out, x, out);
}

// round 14
// speedup vs baseline: 1.4627x; 1.3819x over previous
#include <cuda_runtime.h>
#include <cuda_fp16.h>
#include <cstdint>

// ---------------------------------------------------------------------------
// Problem constants
// ---------------------------------------------------------------------------
#define B_   8
#define C_   256
#define N_   4096
#define G_   8
#define CPG_ 32
#define EPS_ 1e-5f
#define QSCALE_ 0.09016844270216718f   // log2(e)/sqrt(C)

// ---------------------------------------------------------------------------
// Device scratch
// ---------------------------------------------------------------------------
__device__ __half g_xh[(size_t)B_ * N_ * C_];    // GN-applied x, token-major
__device__ __half g_qh[(size_t)B_ * N_ * C_];    // Q token-major, pre-scaled
__device__ __half g_kh[(size_t)B_ * N_ * C_];    // K token-major
__device__ __half g_vh[(size_t)B_ * N_ * C_];    // V token-major
__device__ __half g_oh[(size_t)B_ * N_ * C_];    // attention out, token-major
__device__ __half g_wqh[3 * C_ * C_];            // w_qkv fp16 [o][c]
__device__ __half g_woh[C_ * C_];                // w_out fp16 [o][c]
__device__ float  g_fs[B_ * C_];
__device__ float  g_fb[B_ * C_];

// ---------------------------------------------------------------------------
// Helpers
// ---------------------------------------------------------------------------
__device__ __forceinline__ void mma_f16(float* c,
    uint32_t a0, uint32_t a1, uint32_t a2, uint32_t a3,
    uint32_t b0, uint32_t b1)
{
    asm volatile(
        "mma.sync.aligned.m16n8k16.row.col.f32.f16.f16.f32 "
        "{%0,%1,%2,%3}, {%4,%5,%6,%7}, {%8,%9}, {%0,%1,%2,%3};"
        : "+f"(c[0]), "+f"(c[1]), "+f"(c[2]), "+f"(c[3])
        : "r"(a0), "r"(a1), "r"(a2), "r"(a3), "r"(b0), "r"(b1));
}
__device__ __forceinline__ void ldsm4(uint32_t& r0, uint32_t& r1,
                                      uint32_t& r2, uint32_t& r3, uint32_t addr)
{
    asm volatile("ldmatrix.sync.aligned.m8n8.x4.shared.b16 {%0,%1,%2,%3}, [%4];"
        : "=r"(r0), "=r"(r1), "=r"(r2), "=r"(r3) : "r"(addr));
}
__device__ __forceinline__ void ldsm4t(uint32_t& r0, uint32_t& r1,
                                       uint32_t& r2, uint32_t& r3, uint32_t addr)
{
    asm volatile("ldmatrix.sync.aligned.m8n8.x4.trans.shared.b16 {%0,%1,%2,%3}, [%4];"
        : "=r"(r0), "=r"(r1), "=r"(r2), "=r"(r3) : "r"(addr));
}
__device__ __forceinline__ float ex2f(float x) {
    float r;
    asm("ex2.approx.ftz.f32 %0, %1;" : "=f"(r) : "f"(x));
    return r;
}
__device__ __forceinline__ uint32_t fp2h2(float lo, float hi) {
    __half2 h = __floats2half2_rn(lo, hi);
    return *reinterpret_cast<uint32_t*>(&h);
}
__device__ __forceinline__ uint32_t smem_u32(const void* p) {
    uint32_t a;
    asm("{ .reg .u64 t; cvta.to.shared.u64 t, %1; cvt.u32.u64 %0, t; }"
        : "=r"(a) : "l"(p));
    return a;
}
__device__ __forceinline__ void cp16(uint32_t dst, const void* src) {
    asm volatile("cp.async.cg.shared.global [%0], [%1], 16;"
                 :: "r"(dst), "l"(src) : "memory");
}
#define CP_COMMIT() asm volatile("cp.async.commit_group;" ::: "memory")
#define CP_WAIT0()  asm volatile("cp.async.wait_group 0;" ::: "memory")

// ---------------------------------------------------------------------------
// Kernel 1: GroupNorm stats -> fused per-(b,c) scale/bias
// ---------------------------------------------------------------------------
__global__ __launch_bounds__(256) void gn_stats_kernel(
    const float* __restrict__ x,
    const float* __restrict__ gamma,
    const float* __restrict__ beta)
{
    int b = blockIdx.x >> 3;
    int g = blockIdx.x & 7;
    const float4* p = reinterpret_cast<const float4*>(
        x + ((size_t)(b * C_ + g * CPG_)) * N_);
    float s1 = 0.f, s2 = 0.f;
    for (int i = threadIdx.x; i < 32768; i += 256) {
        float4 v = p[i];
        s1 += (v.x + v.y) + (v.z + v.w);
        s2 += (v.x * v.x + v.y * v.y) + (v.z * v.z + v.w * v.w);
    }
    #pragma unroll
    for (int off = 16; off; off >>= 1) {
        s1 += __shfl_xor_sync(0xffffffffu, s1, off);
        s2 += __shfl_xor_sync(0xffffffffu, s2, off);
    }
    __shared__ float a1[8], a2[8];
    __shared__ float sh_mean, sh_rstd;
    int warp = threadIdx.x >> 5;
    if ((threadIdx.x & 31) == 0) { a1[warp] = s1; a2[warp] = s2; }
    __syncthreads();
    if (threadIdx.x == 0) {
        float t1 = 0.f, t2 = 0.f;
        #pragma unroll
        for (int w = 0; w < 8; w++) { t1 += a1[w]; t2 += a2[w]; }
        float mean = t1 * (1.f / 131072.f);
        float var  = t2 * (1.f / 131072.f) - mean * mean;
        sh_mean = mean;
        sh_rstd = rsqrtf(var + EPS_);
    }
    __syncthreads();
    if (threadIdx.x < CPG_) {
        int c  = g * CPG_ + threadIdx.x;
        float ga = gamma[c];
        float fs = sh_rstd * ga;
        g_fs[b * C_ + c] = fs;
        g_fb[b * C_ + c] = beta[c] - sh_mean * fs;
    }
}

// ---------------------------------------------------------------------------
// Kernel 2a: weights fp32 -> fp16
// ---------------------------------------------------------------------------
__global__ __launch_bounds__(256) void wconv_kernel(
    const float* __restrict__ wq, const float* __restrict__ wo)
{
    int i = blockIdx.x * 256 + threadIdx.x;
    for (int k = i; k < 3 * C_ * C_; k += 65536)
        g_wqh[k] = __float2half(wq[k]);
    if (i < C_ * C_)
        g_woh[i] = __float2half(wo[i]);
}

// ---------------------------------------------------------------------------
// Kernel 2b: xn = GN(x) as fp16 token-major (B, N, C)
// ---------------------------------------------------------------------------
__global__ __launch_bounds__(256) void xn_half_kernel(const float* __restrict__ x)
{
    __shared__ float T[64][65];
    int n0 = blockIdx.x * 256;
    int c0 = blockIdx.y * 64;
    int b  = blockIdx.z;
    int tid = threadIdx.x;
    const float* fsb = g_fs + b * C_;
    const float* fbb = g_fb + b * C_;

    for (int s = 0; s < 4; s++) {
        int nn0 = n0 + s * 64;
        for (int idx = tid; idx < 1024; idx += 256) {
            int cc = idx >> 4, nn4 = (idx & 15) * 4;
            float4 v = *(const float4*)&x[((size_t)(b * C_ + c0 + cc)) * N_ + nn0 + nn4];
            float fs = fsb[c0 + cc], fb = fbb[c0 + cc];
            T[cc][nn4 + 0] = v.x * fs + fb;
            T[cc][nn4 + 1] = v.y * fs + fb;
            T[cc][nn4 + 2] = v.z * fs + fb;
            T[cc][nn4 + 3] = v.w * fs + fb;
        }
        __syncthreads();
        for (int idx = tid; idx < 2048; idx += 256) {
            int nn = idx >> 5, c = (idx & 31) * 2;
            *(uint32_t*)&g_xh[((size_t)b * N_ + nn0 + nn) * C_ + c0 + c] =
                fp2h2(T[c][nn], T[c + 1][nn]);
        }
        __syncthreads();
    }
}

// ---------------------------------------------------------------------------
// Kernel 3: QKV GEMM fp16 mma + ldmatrix. CTA = 128 tokens x 64 outputs.
// grid (N/128, 12, B); type = y>>2. All outputs token-major.
// ---------------------------------------------------------------------------
#define AP 264
#define HG_SMEM ((128 * AP + 64 * AP) * 2)   // 101376 B

__global__ __launch_bounds__(256) void qkv_hgemm_kernel(
    const float* __restrict__ bias)
{
    extern __shared__ __align__(16) char smraw[];
    __half* Ah = (__half*)smraw;
    __half* Bh = Ah + 128 * AP;

    int tid = threadIdx.x;
    int w = tid >> 5, lid = tid & 31;
    int g = lid >> 2, t = lid & 3;
    int wrow = w * 16;
    int n0 = blockIdx.x * 128;
    int o0 = blockIdx.y * 64;
    int b  = blockIdx.z;

    const __half* ag = g_xh + ((size_t)b * N_ + n0) * C_;
    const __half* bg = g_wqh + (size_t)o0 * C_;
    for (int idx = tid; idx < 4096; idx += 256) {
        int r = idx >> 5, c8 = idx & 31;
        *(uint4*)(Ah + r * AP + c8 * 8) = *(const uint4*)(ag + (size_t)r * C_ + c8 * 8);
    }
    for (int idx = tid; idx < 2048; idx += 256) {
        int r = idx >> 5, c8 = idx & 31;
        *(uint4*)(Bh + r * AP + c8 * 8) = *(const uint4*)(bg + (size_t)r * C_ + c8 * 8);
    }
    __syncthreads();

    uint32_t aa = smem_u32(Ah) +
        (uint32_t)(((wrow + (lid & 15)) * AP + (lid >> 4) * 8) * 2);
    uint32_t bb = smem_u32(Bh) +
        (uint32_t)(((((lid & 7) + ((lid >> 4) & 1) * 8)) * AP + ((lid >> 3) & 1) * 8) * 2);

    float acc[8][4];
    #pragma unroll
    for (int nb = 0; nb < 8; nb++)
        #pragma unroll
        for (int j = 0; j < 4; j++) acc[nb][j] = 0.f;

    #pragma unroll 4
    for (int kk = 0; kk < 16; kk++) {
        uint32_t a0, a1, a2, a3;
        ldsm4(a0, a1, a2, a3, aa + kk * 32);
        #pragma unroll
        for (int nbp = 0; nbp < 4; nbp++) {
            uint32_t b0, b1, b2, b3;
            ldsm4(b0, b1, b2, b3, bb + (nbp * 16 * AP + kk * 16) * 2);
            mma_f16(acc[2 * nbp],     a0, a1, a2, a3, b0, b1);
            mma_f16(acc[2 * nbp + 1], a0, a1, a2, a3, b2, b3);
        }
    }

    int type = blockIdx.y >> 2;           // 0 Q, 1 K, 2 V
    int n_lo = n0 + wrow + g;
    float scale = (type == 0) ? QSCALE_ : 1.f;
    __half* gdst = (type == 0 ? g_qh : (type == 1 ? g_kh : g_vh));
    #pragma unroll
    for (int nb = 0; nb < 8; nb++) {
        int og = o0 + nb * 8 + 2 * t;
        int oo = og & 255;
        float b0v = bias[og], b1v = bias[og + 1];
        __half* dst = gdst + ((size_t)b * N_ + n_lo) * C_ + oo;
        *(uint32_t*)dst = fp2h2((acc[nb][0] + b0v) * scale, (acc[nb][1] + b1v) * scale);
        *(uint32_t*)(dst + 8 * C_) = fp2h2((acc[nb][2] + b0v) * scale, (acc[nb][3] + b1v) * scale);
    }
}

// ---------------------------------------------------------------------------
// Kernel 4: flash attention, 256 thr / 8 warps, 128 query rows/CTA.
// KB=64 key blocks (64 iterations): 8 independent S accumulate chains,
// half the barriers. 2-stage cp.async ring. Register-resident P.
// V token-major via ldsm.trans. smem 198KB, 1 CTA/SM.
// ---------------------------------------------------------------------------
#define QPH 264
#define KPH 264
#define VP2 264
#define QWH (128 * QPH)                 // 33792 halves
#define KWH (64 * KPH)                  // 16896 halves
#define VWH (64 * VP2)                  // 16896 halves
#define FL_SMEM ((QWH + 2 * KWH + 2 * VWH) * 2)   // 202752 B

__global__ void __launch_bounds__(256, 1) flash_kernel()
{
    extern __shared__ __align__(16) char smraw[];
    __half* Qh = (__half*)smraw;
    uint32_t sb = smem_u32(smraw);
    uint32_t ka[2], va[2];
    #pragma unroll
    for (int s = 0; s < 2; s++) {
        ka[s] = sb + (QWH + s * KWH) * 2;
        va[s] = sb + (QWH + 2 * KWH + s * VWH) * 2;
    }

    int tid = threadIdx.x;
    int w   = tid >> 5;
    int lid = tid & 31;
    int b   = blockIdx.y;
    int n0  = blockIdx.x * 128;
    int wrow = w * 16;

    const __half* qg = g_qh + ((size_t)b * N_ + n0) * C_;
    const __half* kg = g_kh + (size_t)b * N_ * C_;
    const __half* vg = g_vh + (size_t)b * N_ * C_;

    // cp.async fill coords: K and V tiles are 64 rows x 256 halves
    int kr = tid >> 5, kc8 = tid & 31;   // rows kr + 8*rr

    // prologue: block 0
    #pragma unroll
    for (int rr = 0; rr < 64; rr += 8) {
        cp16(ka[0] + ((kr + rr) * KPH + kc8 * 8) * 2,
             kg + (size_t)(kr + rr) * C_ + kc8 * 8);
        cp16(va[0] + ((kr + rr) * VP2 + kc8 * 8) * 2,
             vg + (size_t)(kr + rr) * C_ + kc8 * 8);
    }
    CP_COMMIT();

    // Q fill (overlaps block-0 arrival; visibility via loop-top sync)
    for (int idx = tid; idx < 4096; idx += 256) {
        int r = idx >> 5, c8 = idx & 31;
        *(uint4*)(Qh + r * QPH + c8 * 8) =
            *(const uint4*)(qg + (size_t)r * C_ + c8 * 8);
    }

    // ldmatrix lane addresses
    uint32_t qa = sb + (uint32_t)(((wrow + (lid & 15)) * QPH + (lid >> 4) * 8) * 2);
    uint32_t kbo = (uint32_t)(((((lid & 7) + ((lid >> 4) & 1) * 8)) * KPH
                               + ((lid >> 3) & 1) * 8) * 2);
    uint32_t vbo = (uint32_t)((((lid & 7) + ((lid >> 3) & 1) * 8) * VP2
                               + (lid >> 4) * 8) * 2);

    float Oacc[32][4];
    #pragma unroll
    for (int nb = 0; nb < 32; nb++)
        #pragma unroll
        for (int j = 0; j < 4; j++) Oacc[nb][j] = 0.f;
    float lsum_lo = 0.f, lsum_hi = 0.f;

    for (int i = 0; i < 64; i++) {
        CP_WAIT0();                      // block i landed (this thread)
        __syncthreads();                 // cross-thread visibility + prev reads done
        if (i < 63) {
            int j = i + 1;
            uint32_t kd = ka[j & 1], vd = va[j & 1];
            #pragma unroll
            for (int rr = 0; rr < 64; rr += 8) {
                cp16(kd + ((kr + rr) * KPH + kc8 * 8) * 2,
                     kg + (size_t)(j * 64 + kr + rr) * C_ + kc8 * 8);
                cp16(vd + ((kr + rr) * VP2 + kc8 * 8) * 2,
                     vg + (size_t)(j * 64 + kr + rr) * C_ + kc8 * 8);
            }
            CP_COMMIT();
        }

        uint32_t kbuf = ka[i & 1] + kbo;
        uint32_t vbuf = va[i & 1] + vbo;

        // ---- S = Q @ K^T : 16 rows x 64 keys, K=256 -> 8 independent chains
        float s[8][4];
        #pragma unroll
        for (int nb = 0; nb < 8; nb++)
            #pragma unroll
            for (int j = 0; j < 4; j++) s[nb][j] = 0.f;
        #pragma unroll 4
        for (int kk = 0; kk < 16; kk++) {
            uint32_t a0, a1, a2, a3;
            ldsm4(a0, a1, a2, a3, qa + kk * 32);
            #pragma unroll
            for (int nbp = 0; nbp < 4; nbp++) {
                uint32_t b0, b1, b2, b3;
                ldsm4(b0, b1, b2, b3, kbuf + (nbp * 16 * KPH + kk * 16) * 2);
                mma_f16(s[2 * nbp],     a0, a1, a2, a3, b0, b1);
                mma_f16(s[2 * nbp + 1], a0, a1, a2, a3, b2, b3);
            }
        }

        // ---- P = exp2(S) entirely in registers (C-frag == PV A-frag)
        float e[8][4];
        #pragma unroll
        for (int nb = 0; nb < 8; nb++) {
            e[nb][0] = ex2f(s[nb][0]);
            e[nb][1] = ex2f(s[nb][1]);
            e[nb][2] = ex2f(s[nb][2]);
            e[nb][3] = ex2f(s[nb][3]);
            lsum_lo += e[nb][0] + e[nb][1];
            lsum_hi += e[nb][2] + e[nb][3];
        }
        uint32_t pf[4][4];
        #pragma unroll
        for (int j = 0; j < 4; j++) {
            pf[j][0] = fp2h2(e[2 * j][0],     e[2 * j][1]);
            pf[j][1] = fp2h2(e[2 * j][2],     e[2 * j][3]);
            pf[j][2] = fp2h2(e[2 * j + 1][0], e[2 * j + 1][1]);
            pf[j][3] = fp2h2(e[2 * j + 1][2], e[2 * j + 1][3]);
        }

        // ---- O += P @ V : 16 rows x 256 channels, K=64 (V via ldsm.trans)
        #pragma unroll 4
        for (int nbp = 0; nbp < 16; nbp++) {
            #pragma unroll
            for (int j = 0; j < 4; j++) {
                uint32_t b0, b1, b2, b3;
                ldsm4t(b0, b1, b2, b3, vbuf + (j * 16 * VP2 + nbp * 16) * 2);
                mma_f16(Oacc[2 * nbp],     pf[j][0], pf[j][1], pf[j][2], pf[j][3], b0, b1);
                mma_f16(Oacc[2 * nbp + 1], pf[j][0], pf[j][1], pf[j][2], pf[j][3], b2, b3);
            }
        }
    }

    // row-sum reduce across the 4 col-group lanes
    lsum_lo += __shfl_xor_sync(0xffffffffu, lsum_lo, 1);
    lsum_lo += __shfl_xor_sync(0xffffffffu, lsum_lo, 2);
    lsum_hi += __shfl_xor_sync(0xffffffffu, lsum_hi, 1);
    lsum_hi += __shfl_xor_sync(0xffffffffu, lsum_hi, 2);
    float inv_lo = 1.f / lsum_lo;
    float inv_hi = 1.f / lsum_hi;

    // epilogue: fp16 O token-major
    int g = lid >> 2, t = lid & 3;
    __half* od = g_oh + ((size_t)b * N_ + n0 + wrow + g) * C_;
    #pragma unroll
    for (int nb = 0; nb < 32; nb++) {
        int c = nb * 8 + 2 * t;
        *(uint32_t*)(od + c) = fp2h2(Oacc[nb][0] * inv_lo, Oacc[nb][1] * inv_lo);
        *(uint32_t*)(od + 8 * C_ + c) = fp2h2(Oacc[nb][2] * inv_hi, Oacc[nb][3] * inv_hi);
    }
}

// ---------------------------------------------------------------------------
// Kernel 5: output projection fp16 mma + ldmatrix + bias + residual.
// CTA = 128 tokens x 64 outputs; grid (N/128, 4, B). 2 CTAs/SM.
// ---------------------------------------------------------------------------
__global__ __launch_bounds__(256) void proj_hgemm_kernel(
    const float* __restrict__ bias,
    const float* __restrict__ x,
    float* __restrict__ out)
{
    extern __shared__ __align__(16) char smraw[];
    __half* Ah = (__half*)smraw;
    __half* Bh = Ah + 128 * AP;
    float* Ts  = (float*)smraw;          // reused after compute: 64 x 136

    int tid = threadIdx.x;
    int w = tid >> 5, lid = tid & 31;
    int g = lid >> 2, t = lid & 3;
    int wrow = w * 16;
    int n0 = blockIdx.x * 128;
    int o0 = blockIdx.y * 64;
    int b  = blockIdx.z;

    const __half* ag = g_oh + ((size_t)b * N_ + n0) * C_;
    const __half* bg = g_woh + (size_t)o0 * C_;
    for (int idx = tid; idx < 4096; idx += 256) {
        int r = idx >> 5, c8 = idx & 31;
        *(uint4*)(Ah + r * AP + c8 * 8) = *(const uint4*)(ag + (size_t)r * C_ + c8 * 8);
    }
    for (int idx = tid; idx < 2048; idx += 256) {
        int r = idx >> 5, c8 = idx & 31;
        *(uint4*)(Bh + r * AP + c8 * 8) = *(const uint4*)(bg + (size_t)r * C_ + c8 * 8);
    }
    __syncthreads();

    uint32_t aa = smem_u32(Ah) +
        (uint32_t)(((wrow + (lid & 15)) * AP + (lid >> 4) * 8) * 2);
    uint32_t bb = smem_u32(Bh) +
        (uint32_t)(((((lid & 7) + ((lid >> 4) & 1) * 8)) * AP + ((lid >> 3) & 1) * 8) * 2);

    float acc[8][4];
    #pragma unroll
    for (int nb = 0; nb < 8; nb++)
        #pragma unroll
        for (int j = 0; j < 4; j++) acc[nb][j] = 0.f;

    #pragma unroll 4
    for (int kk = 0; kk < 16; kk++) {
        uint32_t a0, a1, a2, a3;
        ldsm4(a0, a1, a2, a3, aa + kk * 32);
        #pragma unroll
        for (int nbp = 0; nbp < 4; nbp++) {
            uint32_t b0, b1, b2, b3;
            ldsm4(b0, b1, b2, b3, bb + (nbp * 16 * AP + kk * 16) * 2);
            mma_f16(acc[2 * nbp],     a0, a1, a2, a3, b0, b1);
            mma_f16(acc[2 * nbp + 1], a0, a1, a2, a3, b2, b3);
        }
    }

    // stage D transposed [o_local][token] in fp32
    __syncthreads();
    #pragma unroll
    for (int nb = 0; nb < 8; nb++) {
        int ol = nb * 8 + 2 * t;
        Ts[ol * 136 + wrow + g]           = acc[nb][0];
        Ts[(ol + 1) * 136 + wrow + g]     = acc[nb][1];
        Ts[ol * 136 + wrow + g + 8]       = acc[nb][2];
        Ts[(ol + 1) * 136 + wrow + g + 8] = acc[nb][3];
    }
    __syncthreads();

    for (int idx = tid; idx < 2048; idx += 256) {
        int o = idx >> 5, n4 = (idx & 31) * 4;
        int og = o0 + o;
        float bo = bias[og];
        size_t base = ((size_t)b * C_ + og) * N_ + n0 + n4;
        float4 res = *(const float4*)&x[base];
        float4 d   = *(const float4*)&Ts[o * 136 + n4];
        float4 r = make_float4(d.x + bo + res.x, d.y + bo + res.y,
                               d.z + bo + res.z, d.w + bo + res.w);
        *(float4*)&out[base] = r;
    }
}

// ---------------------------------------------------------------------------
// Launch
// ---------------------------------------------------------------------------
extern "C" void kernel_launch(void* const* d_in, const int* in_sizes, int n_in,
                              void* d_out, int out_size)
{
    const float* x        = (const float*)d_in[0];
    const float* gn_scale = (const float*)d_in[1];
    const float* gn_bias  = (const float*)d_in[2];
    const float* w_qkv    = (const float*)d_in[3];
    const float* b_qkv    = (const float*)d_in[4];
    const float* w_out    = (const float*)d_in[5];
    const float* b_out    = (const float*)d_in[6];
    float* out = (float*)d_out;

    cudaFuncSetAttribute(flash_kernel,
                         cudaFuncAttributeMaxDynamicSharedMemorySize, FL_SMEM);
    cudaFuncSetAttribute(qkv_hgemm_kernel,
                         cudaFuncAttributeMaxDynamicSharedMemorySize, HG_SMEM);
    cudaFuncSetAttribute(proj_hgemm_kernel,
                         cudaFuncAttributeMaxDynamicSharedMemorySize, HG_SMEM);

    wconv_kernel<<<256, 256>>>(w_qkv, w_out);
    gn_stats_kernel<<<B_ * G_, 256>>>(x, gn_scale, gn_bias);
    xn_half_kernel<<<dim3(N_ / 256, C_ / 64, B_), 256>>>(x);
    qkv_hgemm_kernel<<<dim3(N_ / 128, 12, B_), 256, HG_SMEM>>>(b_qkv);
    flash_kernel<<<dim3(N_ / 128, B_), 256, FL_SMEM>>>();
    proj_hgemm_kernel<<<dim3(N_ / 128, 4, B_), 256, HG_SMEM>>>(b_out, x, out);
}